// round 13
// baseline (speedup 1.0000x reference)
#include <cuda_runtime.h>
#include <cuda_fp16.h>
#include <math.h>
#include <stdint.h>

// Problem constants
#define B_SZ    512
#define N_SZ    256
#define N_ITERS 400
#define LAMBD   1.0f
#define KAPPA   0.1f

// 32x32 tiles over the 8x8 tile-grid upper triangle: 36 tiles per matrix.
#define NTILES 36
__constant__ int c_TA[NTILES] = {0,0,0,0,0,0,0,0, 1,1,1,1,1,1,1, 2,2,2,2,2,2,
                                 3,3,3,3,3, 4,4,4,4, 5,5,5, 6,6, 7};
__constant__ int c_TB[NTILES] = {0,1,2,3,4,5,6,7, 1,2,3,4,5,6,7, 2,3,4,5,6,7,
                                 3,4,5,6,7, 4,5,6,7, 5,6,7, 6,7, 7};

__device__ __forceinline__ int tri_idx(int a, int b) {  // a <= b
    return a * 8 - (a * (a - 1)) / 2 + (b - a);
}

// fp16 G tile store: 32 rows x 40 halves (80B stride)
#define TILE_STRIDE_B 80
#define TILE_BYTES    (32 * TILE_STRIDE_B)      // 2560
#define MAT_BYTES     (NTILES * TILE_BYTES)     // 92160
#define BATCH_BYTES   (2 * MAT_BYTES)           // 184320

__device__ unsigned char g_G16[(size_t)B_SZ * BATCH_BYTES];  // ~94 MB
__device__ float g_fro[2 * B_SZ];

// ---------------------------------------------------------------------------
// PTX helpers (sm_90-baseline cluster ops + ldmatrix/mma; no 'a'-gated ops)
// ---------------------------------------------------------------------------
__device__ __forceinline__ uint32_t smem_u32(const void* p) {
    uint32_t a;
    asm("{ .reg .u64 t; cvta.to.shared.u64 t, %1; cvt.u32.u64 %0, t; }"
        : "=r"(a) : "l"(p));
    return a;
}
__device__ __forceinline__ uint32_t cl_rank() {
    uint32_t r;
    asm("mov.u32 %0, %%cluster_ctarank;" : "=r"(r));
    return r;
}
__device__ __forceinline__ uint32_t mapa_peer(uint32_t laddr, uint32_t rank) {
    uint32_t r;
    asm volatile("mapa.shared::cluster.u32 %0, %1, %2;"
                 : "=r"(r) : "r"(laddr), "r"(rank));
    return r;
}
__device__ __forceinline__ void st_cl_f32(uint32_t addr, float v) {
    asm volatile("st.shared::cluster.f32 [%0], %1;" :: "r"(addr), "f"(v) : "memory");
}
__device__ __forceinline__ void mbar_init(uint32_t a, uint32_t cnt) {
    asm volatile("mbarrier.init.shared.b64 [%0], %1;" :: "r"(a), "r"(cnt) : "memory");
}
__device__ __forceinline__ void mbar_arrive_cl(uint32_t peer_addr) {
    asm volatile("mbarrier.arrive.release.cluster.shared::cluster.b64 _, [%0];"
                 :: "r"(peer_addr) : "memory");
}
__device__ __forceinline__ void mbar_wait_cl(uint32_t a, uint32_t parity) {
    asm volatile(
        "{\n\t.reg .pred P;\n\t"
        "WAITL_%=:\n\t"
        "mbarrier.try_wait.parity.acquire.cluster.shared::cta.b64 P, [%0], %1;\n\t"
        "@P bra.uni WAITD_%=;\n\t"
        "bra.uni WAITL_%=;\n\t"
        "WAITD_%=:\n\t}" :: "r"(a), "r"(parity) : "memory");
}
#define CLUSTER_SYNC() do { \
    asm volatile("barrier.cluster.arrive.aligned;" ::: "memory"); \
    asm volatile("barrier.cluster.wait.aligned;" ::: "memory"); \
} while (0)

__device__ __forceinline__ void ldsm4(uint32_t& a0, uint32_t& a1, uint32_t& a2,
                                      uint32_t& a3, uint32_t addr) {
    asm volatile("ldmatrix.sync.aligned.m8n8.x4.shared.b16 {%0,%1,%2,%3}, [%4];"
                 : "=r"(a0), "=r"(a1), "=r"(a2), "=r"(a3) : "r"(addr));
}
__device__ __forceinline__ void ldsm4t(uint32_t& a0, uint32_t& a1, uint32_t& a2,
                                       uint32_t& a3, uint32_t addr) {
    asm volatile("ldmatrix.sync.aligned.m8n8.x4.trans.shared.b16 {%0,%1,%2,%3}, [%4];"
                 : "=r"(a0), "=r"(a1), "=r"(a2), "=r"(a3) : "r"(addr));
}
__device__ __forceinline__ void ldsm2t(uint32_t& r0, uint32_t& r1, uint32_t addr) {
    asm volatile("ldmatrix.sync.aligned.m8n8.x2.trans.shared.b16 {%0,%1}, [%2];"
                 : "=r"(r0), "=r"(r1) : "r"(addr));
}
__device__ __forceinline__ void mma16816(float* c, uint32_t a0, uint32_t a1,
                                         uint32_t a2, uint32_t a3,
                                         uint32_t b0, uint32_t b1) {
    asm volatile(
        "mma.sync.aligned.m16n8k16.row.col.f32.f16.f16.f32 "
        "{%0,%1,%2,%3}, {%4,%5,%6,%7}, {%8,%9}, {%0,%1,%2,%3};"
        : "+f"(c[0]), "+f"(c[1]), "+f"(c[2]), "+f"(c[3])
        : "r"(a0), "r"(a1), "r"(a2), "r"(a3), "r"(b0), "r"(b1));
}

// ---------------------------------------------------------------------------
// Kernel 1: batched SYRK via HMMA with split-fp16 inputs (unchanged from R8).
// ---------------------------------------------------------------------------
#define XS_STRIDE 528
#define XS_LBASE  (128 * XS_STRIDE)
#define XS_SCR    (2 * 128 * XS_STRIDE)
#define SYRK_SMEM (XS_SCR + 64)

__global__ __launch_bounds__(256, 1) void syrk16_kernel(const float* __restrict__ U,
                                                        const float* __restrict__ A) {
    extern __shared__ unsigned char sm[];
    const uint32_t smb = smem_u32(sm);
    const int mat = blockIdx.x >> 9;
    const int b = blockIdx.x & (B_SZ - 1);
    const float* __restrict__ X = (mat ? A : U) + (size_t)b * (N_SZ * N_SZ);
    const int t = threadIdx.x;
    const int lane = t & 31;
    const int w = t >> 5;

    const uint32_t lane_tr = (uint32_t)((lane & 7) + ((lane & 16) >> 1)) * XS_STRIDE
                           + (uint32_t)(lane & 8) * 2;
    const uint32_t laneB = (uint32_t)(lane & 15) * XS_STRIDE;

    float fro = 0.f;
    float acc[5][2][4][4];
    #pragma unroll
    for (int q = 0; q < 5; q++)
        #pragma unroll
        for (int mh = 0; mh < 2; mh++)
            #pragma unroll
            for (int nq = 0; nq < 4; nq++)
                #pragma unroll
                for (int e = 0; e < 4; e++) acc[q][mh][nq][e] = 0.f;

    #pragma unroll 1
    for (int ch = 0; ch < 2; ch++) {
        if (ch) __syncthreads();
        #pragma unroll 4
        for (int idx = t; idx < 128 * 128; idx += 256) {
            const int ir = idx >> 7;
            const int jp = idx & 127;
            const float2 f = *(const float2*)(X + (size_t)(128 * ch + ir) * N_SZ + 2 * jp);
            fro = fmaf(f.x, f.x, fro);
            fro = fmaf(f.y, f.y, fro);
            const __half hx = __float2half_rn(f.x);
            const __half hy = __float2half_rn(f.y);
            const __half lx = __float2half_rn(f.x - __half2float(hx));
            const __half ly = __float2half_rn(f.y - __half2float(hy));
            *(__half2*)(sm + ir * XS_STRIDE + jp * 4) = __halves2half2(hx, hy);
            *(__half2*)(sm + XS_LBASE + ir * XS_STRIDE + jp * 4) = __halves2half2(lx, ly);
        }
        __syncthreads();

        #pragma unroll
        for (int q = 0; q < 5; q++) {
            const int tix = w + 8 * q;
            if (tix < NTILES) {
                const int a0 = c_TA[tix], b0 = c_TB[tix];
                const uint32_t acol = smb + (uint32_t)(a0 * 32) * 2 + lane_tr;
                const uint32_t bcol = smb + (uint32_t)(b0 * 32) * 2 + laneB;
                #pragma unroll
                for (int kc = 0; kc < 8; kc++) {
                    const uint32_t ro = (uint32_t)(kc * 16) * XS_STRIDE;
                    uint32_t AH[2][4], AL[2][4];
                    #pragma unroll
                    for (int mh = 0; mh < 2; mh++) {
                        const uint32_t ao = acol + ro + (uint32_t)(mh * 16) * 2;
                        ldsm4t(AH[mh][0], AH[mh][1], AH[mh][2], AH[mh][3], ao);
                        ldsm4t(AL[mh][0], AL[mh][1], AL[mh][2], AL[mh][3],
                               ao + XS_LBASE);
                    }
                    #pragma unroll
                    for (int nq = 0; nq < 4; nq++) {
                        const uint32_t bo = bcol + ro + (uint32_t)(nq * 8) * 2;
                        uint32_t bh0, bh1, bl0, bl1;
                        ldsm2t(bh0, bh1, bo);
                        ldsm2t(bl0, bl1, bo + XS_LBASE);
                        #pragma unroll
                        for (int mh = 0; mh < 2; mh++) {
                            float* c = acc[q][mh][nq];
                            mma16816(c, AH[mh][0], AH[mh][1], AH[mh][2], AH[mh][3],
                                     bh0, bh1);
                            mma16816(c, AH[mh][0], AH[mh][1], AH[mh][2], AH[mh][3],
                                     bl0, bl1);
                            mma16816(c, AL[mh][0], AL[mh][1], AL[mh][2], AL[mh][3],
                                     bh0, bh1);
                        }
                    }
                }
            }
        }
    }

    unsigned char* gb = g_G16 + (size_t)b * BATCH_BYTES + (size_t)mat * MAT_BYTES;
    #pragma unroll
    for (int q = 0; q < 5; q++) {
        const int tix = w + 8 * q;
        if (tix < NTILES) {
            #pragma unroll
            for (int mh = 0; mh < 2; mh++)
                #pragma unroll
                for (int nq = 0; nq < 4; nq++) {
                    const float* c = acc[q][mh][nq];
                    const uint32_t o = (uint32_t)tix * TILE_BYTES
                        + (uint32_t)(mh * 16 + (lane >> 2)) * TILE_STRIDE_B
                        + (uint32_t)(nq * 4 + (lane & 3)) * 4;
                    *(__half2*)(gb + o) =
                        __halves2half2(__float2half_rn(c[0]), __float2half_rn(c[1]));
                    *(__half2*)(gb + o + 8 * TILE_STRIDE_B) =
                        __halves2half2(__float2half_rn(c[2]), __float2half_rn(c[3]));
                }
        }
    }

    #pragma unroll
    for (int o = 16; o; o >>= 1) fro += __shfl_xor_sync(0xFFFFFFFFu, fro, o);
    float* scr = (float*)(sm + XS_SCR);
    if (lane == 0) scr[w] = fro;
    __syncthreads();
    if (t == 0) {
        float s = 0.f;
        #pragma unroll
        for (int qq = 0; qq < 8; qq++) s += scr[qq];
        g_fro[mat * B_SZ + b] = s;
    }
}

// ---------------------------------------------------------------------------
// Kernel 2: cluster-split PGD. Cluster of 2 CTAs per batch: rank0 owns G1,
// rank1 owns G2. Each CTA: 8 warps, band-per-warp matvec of ITS matrix only
// (3 register-resident k-bands, 5 streamed). y (and G2's w.G2w partials) are
// written into BOTH CTAs' smem via st.shared::cluster; per-warp
// mbarrier.arrive.release.cluster on the peer (8 arrivals), parity
// double-buffered. Both CTAs then run the identical replicated projection ->
// bitwise-identical w. 2 CTAs/SM (smem ~100KB, regs <=128).
// ---------------------------------------------------------------------------
#define CL_SM_MBAR   0                       // 2 x 8B mbarriers
#define CL_SM_PROD   64                      // [2][8] f32
#define CL_SM_W      256                     // 8 warps x 512B packed w
#define CL_SM_Y1     4608                    // [2][256] f32 transposed
#define CL_SM_Y2     6656                    // [2][256] f32 transposed
#define CL_SM_MU     8704                    // 256 f32 transposed
#define CL_SM_TILES  10240                   // 36 tiles x 2560
#define CL_SM_TOTAL  (CL_SM_TILES + MAT_BYTES)   // 102400

__global__ __launch_bounds__(256, 2) __cluster_dims__(2, 1, 1)
void pgd_cl_kernel(const float* __restrict__ mu, float* __restrict__ out) {
    extern __shared__ unsigned char sm[];
    const uint32_t smb = smem_u32(sm);
    const int t = threadIdx.x;
    const int lane = t & 31;
    const int r = t >> 5;                    // warp id == output band
    const uint32_t rank = cl_rank();         // 0 -> G1, 1 -> G2
    const uint32_t peer = rank ^ 1u;
    const int b = blockIdx.x >> 1;

    // ---- init: mbarriers, my matrix triangle, mu (transposed) ----
    if (t == 0) {
        mbar_init(smb + CL_SM_MBAR, 8);
        mbar_init(smb + CL_SM_MBAR + 8, 8);
    }
    {
        const uint4* src = (const uint4*)(g_G16 + (size_t)b * BATCH_BYTES
                                          + (size_t)rank * MAT_BYTES);
        uint4* dst = (uint4*)(sm + CL_SM_TILES);
        #pragma unroll 4
        for (int i = t; i < MAT_BYTES / 16; i += 256) dst[i] = src[i];
        ((float*)(sm + CL_SM_MU))[(t & 31) * 8 + (t >> 5)] = mu[(size_t)b * N_SZ + t];
    }

    const uint32_t tb = smb + CL_SM_TILES;
    const uint32_t wpriv = smb + CL_SM_W + (uint32_t)r * 512;

    const uint32_t lane_nt = (uint32_t)((lane & 7) + (lane & 8)) * TILE_STRIDE_B
                           + (uint32_t)((lane & 16) >> 1) * 2;
    const uint32_t lane_tr = (uint32_t)((lane & 7) + ((lane & 16) >> 1)) * TILE_STRIDE_B
                           + (uint32_t)(lane & 8) * 2;

    // packed-w writer offset (R12 layout)
    const int pw = lane & 15;
    const uint32_t lane_woff = (uint32_t)(((lane >> 4) & 1) * 4 + ((pw >> 1) & 3)) * 8
                             + (uint32_t)((((pw >> 3) << 1) | (pw & 1)) * 2);

    const float step = 1.0f / (LAMBD * g_fro[b] + KAPPA * sqrtf(g_fro[B_SZ + b]) + 1.0f);

    __syncthreads();

    // ---- preload k-bands 0..2 of MY matrix into registers (48 regs) ----
    uint32_t fr[3][2][2][4];
    #pragma unroll
    for (int bb = 0; bb < 3; bb++) {
        const bool trp = (bb < r);
        const int aa = trp ? bb : r;
        const int bn = trp ? r : bb;
        const uint32_t tile = tb + (uint32_t)tri_idx(aa, bn) * TILE_BYTES;
        #pragma unroll
        for (int ks = 0; ks < 2; ks++) {
            if (trp) {
                const uint32_t o = (uint32_t)ks * (16 * TILE_STRIDE_B) + lane_tr;
                ldsm4t(fr[bb][ks][0][0], fr[bb][ks][0][1],
                       fr[bb][ks][0][2], fr[bb][ks][0][3], tile + o);
                ldsm4t(fr[bb][ks][1][0], fr[bb][ks][1][1],
                       fr[bb][ks][1][2], fr[bb][ks][1][3], tile + o + 32);
            } else {
                const uint32_t o = (uint32_t)ks * 32 + lane_nt;
                ldsm4(fr[bb][ks][0][0], fr[bb][ks][0][1],
                      fr[bb][ks][0][2], fr[bb][ks][0][3], tile + o);
                ldsm4(fr[bb][ks][1][0], fr[bb][ks][1][1],
                      fr[bb][ks][1][2], fr[bb][ks][1][3],
                      tile + o + 16 * TILE_STRIDE_B);
            }
        }
    }

    // ---- replicated solver state ----
    float wv[8];
    float tau = 0.0f;
    #pragma unroll
    for (int k = 0; k < 8; k++) {
        wv[k] = 1.0f / (float)N_SZ;
        const __half h = __float2half_rn(wv[k]);
        asm volatile("st.shared.u16 [%0], %1;"
                     :: "r"(wpriv + (uint32_t)k * 64 + lane_woff),
                        "h"(__half_as_ushort(h)) : "memory");
    }
    __syncwarp();
    __syncthreads();
    CLUSTER_SYNC();   // peer mbarriers + smem ready before any remote op

    int ph0 = 0, ph1 = 0;   // phase parity per buffer

    #pragma unroll 1
    for (int it = 0; it < N_ITERS; it++) {
        const uint32_t buf = (uint32_t)(it & 1);
        float* const y1s = (float*)(sm + CL_SM_Y1 + buf * 1024);
        float* const y2s = (float*)(sm + CL_SM_Y2 + buf * 1024);
        float* const prods = (float*)(sm + CL_SM_PROD + buf * 32);
        const uint32_t ymine_off = (rank ? CL_SM_Y2 : CL_SM_Y1) + buf * 1024;

        float cA[4] = {0.f,0.f,0.f,0.f}, cB[4] = {0.f,0.f,0.f,0.f};

        // ---- k-bands 0..2: register-resident ----
        #pragma unroll
        for (int bb = 0; bb < 3; bb++) {
            #pragma unroll
            for (int ks = 0; ks < 2; ks++) {
                uint32_t b0, b1;
                const uint32_t waddr = wpriv + (uint32_t)((bb * 8 + ks * 4) * 8)
                                     + (uint32_t)(lane & 3) * 8;
                asm volatile("ld.shared.v2.b32 {%0,%1}, [%2];"
                             : "=r"(b0), "=r"(b1) : "r"(waddr));
                if (lane >= 4) { b0 = 0u; b1 = 0u; }
                mma16816(cA, fr[bb][ks][0][0], fr[bb][ks][0][1],
                             fr[bb][ks][0][2], fr[bb][ks][0][3], b0, b1);
                mma16816(cB, fr[bb][ks][1][0], fr[bb][ks][1][1],
                             fr[bb][ks][1][2], fr[bb][ks][1][3], b0, b1);
            }
        }

        // ---- k-bands 3..7: batched LDSM then MMA ----
        #pragma unroll
        for (int bb = 3; bb < 8; bb++) {
            const bool trp = (bb < r);
            const int aa = trp ? bb : r;
            const int bn = trp ? r : bb;
            const uint32_t tile = tb + (uint32_t)tri_idx(aa, bn) * TILE_BYTES;
            #pragma unroll
            for (int ks = 0; ks < 2; ks++) {
                uint32_t b0, b1;
                const uint32_t waddr = wpriv + (uint32_t)((bb * 8 + ks * 4) * 8)
                                     + (uint32_t)(lane & 3) * 8;
                asm volatile("ld.shared.v2.b32 {%0,%1}, [%2];"
                             : "=r"(b0), "=r"(b1) : "r"(waddr));
                if (lane >= 4) { b0 = 0u; b1 = 0u; }

                uint32_t sA[2][4];
                if (trp) {
                    const uint32_t o = (uint32_t)ks * (16 * TILE_STRIDE_B) + lane_tr;
                    ldsm4t(sA[0][0], sA[0][1], sA[0][2], sA[0][3], tile + o);
                    ldsm4t(sA[1][0], sA[1][1], sA[1][2], sA[1][3], tile + o + 32);
                } else {
                    const uint32_t o = (uint32_t)ks * 32 + lane_nt;
                    ldsm4(sA[0][0], sA[0][1], sA[0][2], sA[0][3], tile + o);
                    ldsm4(sA[1][0], sA[1][1], sA[1][2], sA[1][3],
                          tile + o + 16 * TILE_STRIDE_B);
                }
                mma16816(cA, sA[0][0], sA[0][1], sA[0][2], sA[0][3], b0, b1);
                mma16816(cB, sA[1][0], sA[1][1], sA[1][2], sA[1][3], b0, b1);
            }
        }

        // ---- publish y band (transposed idx) locally AND to peer ----
        const int g = lane >> 2;
        if ((lane & 3) == 0) {
            const uint32_t o0 = smb + ymine_off + (uint32_t)(g * 8 + r) * 4;
            const uint32_t o1 = smb + ymine_off + (uint32_t)((g + 8) * 8 + r) * 4;
            const uint32_t o2 = smb + ymine_off + (uint32_t)((g + 16) * 8 + r) * 4;
            const uint32_t o3 = smb + ymine_off + (uint32_t)((g + 24) * 8 + r) * 4;
            *(float*)(sm + (o0 - smb)) = cA[0];
            *(float*)(sm + (o1 - smb)) = cA[2];
            *(float*)(sm + (o2 - smb)) = cB[0];
            *(float*)(sm + (o3 - smb)) = cB[2];
            st_cl_f32(mapa_peer(o0, peer), cA[0]);
            st_cl_f32(mapa_peer(o1, peer), cA[2]);
            st_cl_f32(mapa_peer(o2, peer), cB[0]);
            st_cl_f32(mapa_peer(o3, peer), cB[2]);
        }
        if (rank == 1) {   // w . (G2 w) partial for band r
            const float wg0 = __shfl_sync(0xFFFFFFFFu, wv[r], g);
            const float wg1 = __shfl_sync(0xFFFFFFFFu, wv[r], g + 8);
            const float wg2 = __shfl_sync(0xFFFFFFFFu, wv[r], g + 16);
            const float wg3 = __shfl_sync(0xFFFFFFFFu, wv[r], g + 24);
            float p = cA[0] * wg0 + cA[2] * wg1 + cB[0] * wg2 + cB[2] * wg3;
            p += __shfl_xor_sync(0xFFFFFFFFu, p, 4);
            p += __shfl_xor_sync(0xFFFFFFFFu, p, 8);
            p += __shfl_xor_sync(0xFFFFFFFFu, p, 16);
            if (lane == 0) {
                const uint32_t po = smb + CL_SM_PROD + buf * 32 + (uint32_t)r * 4;
                *(float*)(sm + (po - smb)) = p;
                st_cl_f32(mapa_peer(po, peer), p);
            }
        }
        __syncwarp();
        if (lane == 0)
            mbar_arrive_cl(mapa_peer(smb + CL_SM_MBAR + buf * 8, peer));

        __syncthreads();                           // local y visibility
        mbar_wait_cl(smb + CL_SM_MBAR + buf * 8,   // peer data ready
                     (uint32_t)(buf ? ph1 : ph0));
        if (buf) ph1 ^= 1; else ph0 ^= 1;

        // ---- replicated projection (identical in both CTAs, all warps) ----
        float4 pv0 = *(const float4*)prods;
        float4 pv1 = *(const float4*)(prods + 4);
        const float pr = ((pv0.x + pv0.y) + (pv0.z + pv0.w))
                       + ((pv1.x + pv1.y) + (pv1.z + pv1.w));
        const float nrm = sqrtf(fmaxf(pr, 1e-12f));
        const float kin = KAPPA / nrm;

        float v[8];
        {
            const float4 a0 = *(const float4*)(y1s + lane * 8);
            const float4 a1 = *(const float4*)(y1s + lane * 8 + 4);
            const float4 b0v = *(const float4*)(y2s + lane * 8);
            const float4 b1v = *(const float4*)(y2s + lane * 8 + 4);
            const float4 m0 = *(const float4*)((float*)(sm + CL_SM_MU) + lane * 8);
            const float4 m1 = *(const float4*)((float*)(sm + CL_SM_MU) + lane * 8 + 4);
            v[0] = wv[0] - step * (-m0.x + LAMBD * a0.x + kin * b0v.x);
            v[1] = wv[1] - step * (-m0.y + LAMBD * a0.y + kin * b0v.y);
            v[2] = wv[2] - step * (-m0.z + LAMBD * a0.z + kin * b0v.z);
            v[3] = wv[3] - step * (-m0.w + LAMBD * a0.w + kin * b0v.w);
            v[4] = wv[4] - step * (-m1.x + LAMBD * a1.x + kin * b1v.x);
            v[5] = wv[5] - step * (-m1.y + LAMBD * a1.y + kin * b1v.y);
            v[6] = wv[6] - step * (-m1.z + LAMBD * a1.z + kin * b1v.z);
            v[7] = wv[7] - step * (-m1.w + LAMBD * a1.w + kin * b1v.w);
        }

        // Warm-started Newton on f(tau) = sum(relu(v-tau)) - 1.
        float tt = tau;
        bool fb = false;
        for (int ni = 0; ni < 12; ni++) {
            float s = 0.f;
            int cnt = 0;
            #pragma unroll
            for (int k = 0; k < 8; k++) {
                const float d = v[k] - tt;
                if (d > 0.f) { s += d; cnt++; }
            }
            cnt = __reduce_add_sync(0xFFFFFFFFu, cnt);
            #pragma unroll
            for (int o = 16; o; o >>= 1)
                s += __shfl_xor_sync(0xFFFFFFFFu, s, o);
            if (cnt == 0) {
                if (fb) break;
                fb = true;
                float S = 0.f;
                #pragma unroll
                for (int k = 0; k < 8; k++) S += v[k];
                #pragma unroll
                for (int o = 16; o; o >>= 1)
                    S += __shfl_xor_sync(0xFFFFFFFFu, S, o);
                tt = (S - 1.0f) * (1.0f / (float)N_SZ);
                continue;
            }
            const float delta = (s - 1.0f) / (float)cnt;
            tt += delta;
            if (fabsf(delta) <= 1e-10f) break;
        }
        tau = tt;

        #pragma unroll
        for (int k = 0; k < 8; k++) {
            wv[k] = fmaxf(v[k] - tau, 0.f);
            const __half h = __float2half_rn(wv[k]);
            asm volatile("st.shared.u16 [%0], %1;"
                         :: "r"(wpriv + (uint32_t)k * 64 + lane_woff),
                            "h"(__half_as_ushort(h)) : "memory");
        }
        __syncwarp();
    }

    // ---- final clamp + renormalize (rank0 warp0 writes) ----
    if (rank == 0 && r == 0) {
        float s = 0.f;
        #pragma unroll
        for (int k = 0; k < 8; k++) { wv[k] = fmaxf(wv[k], 0.f); s += wv[k]; }
        #pragma unroll
        for (int o = 16; o; o >>= 1) s += __shfl_xor_sync(0xFFFFFFFFu, s, o);
        const float inv = 1.0f / (s + 1e-12f);
        #pragma unroll
        for (int k = 0; k < 8; k++)
            out[(size_t)b * N_SZ + lane + (k << 5)] = wv[k] * inv;
    }

    CLUSTER_SYNC();   // no CTA exits while peer may still touch its smem
}

// ---------------------------------------------------------------------------
// Launcher
// ---------------------------------------------------------------------------
extern "C" void kernel_launch(void* const* d_in, const int* in_sizes, int n_in,
                              void* d_out, int out_size) {
    const float* mu = (const float*)d_in[0];
    const float* U  = (const float*)d_in[1];
    const float* A  = (const float*)d_in[2];
    float* out = (float*)d_out;

    cudaFuncSetAttribute(syrk16_kernel, cudaFuncAttributeMaxDynamicSharedMemorySize,
                         SYRK_SMEM);
    cudaFuncSetAttribute(pgd_cl_kernel, cudaFuncAttributeMaxDynamicSharedMemorySize,
                         CL_SM_TOTAL);

    syrk16_kernel<<<2 * B_SZ, 256, SYRK_SMEM>>>(U, A);
    pgd_cl_kernel<<<2 * B_SZ, 256, CL_SM_TOTAL>>>(mu, out);
}

// round 14
// speedup vs baseline: 1.4378x; 1.4378x over previous
#include <cuda_runtime.h>
#include <cuda_fp16.h>
#include <math.h>
#include <stdint.h>

// Problem constants
#define B_SZ    512
#define N_SZ    256
#define N_ITERS 400
#define LAMBD   1.0f
#define KAPPA   0.1f

// 32x32 tiles over the 8x8 tile-grid upper triangle: 36 tiles (G1 only now).
#define NTILES 36
__constant__ int c_TA[NTILES] = {0,0,0,0,0,0,0,0, 1,1,1,1,1,1,1, 2,2,2,2,2,2,
                                 3,3,3,3,3, 4,4,4,4, 5,5,5, 6,6, 7};
__constant__ int c_TB[NTILES] = {0,1,2,3,4,5,6,7, 1,2,3,4,5,6,7, 2,3,4,5,6,7,
                                 3,4,5,6,7, 4,5,6,7, 5,6,7, 6,7, 7};

__device__ __forceinline__ int tri_idx(int a, int b) {  // a <= b
    return a * 8 - (a * (a - 1)) / 2 + (b - a);
}

// fp16 G1 tile store: 32 rows x 40 halves (80B stride)
#define TILE_STRIDE_B 80
#define TILE_BYTES    (32 * TILE_STRIDE_B)      // 2560
#define MAT_BYTES     (NTILES * TILE_BYTES)     // 92160

// Global scratch: G1 triangle tiles (fp16), G2 full row-major fp16, Frobenius.
__device__ unsigned char g_G16[(size_t)B_SZ * MAT_BYTES];          // ~47 MB
__device__ unsigned short g_G2R[(size_t)B_SZ * N_SZ * N_SZ];        // 64 MB
__device__ float g_fro[2 * B_SZ];

// ---------------------------------------------------------------------------
// PTX helpers (base PTX only; no 'a'-gated instructions)
// ---------------------------------------------------------------------------
__device__ __forceinline__ uint32_t smem_u32(const void* p) {
    uint32_t a;
    asm("{ .reg .u64 t; cvta.to.shared.u64 t, %1; cvt.u32.u64 %0, t; }"
        : "=r"(a) : "l"(p));
    return a;
}
__device__ __forceinline__ void ldsm4(uint32_t& a0, uint32_t& a1, uint32_t& a2,
                                      uint32_t& a3, uint32_t addr) {
    asm volatile("ldmatrix.sync.aligned.m8n8.x4.shared.b16 {%0,%1,%2,%3}, [%4];"
                 : "=r"(a0), "=r"(a1), "=r"(a2), "=r"(a3) : "r"(addr));
}
__device__ __forceinline__ void ldsm4t(uint32_t& a0, uint32_t& a1, uint32_t& a2,
                                       uint32_t& a3, uint32_t addr) {
    asm volatile("ldmatrix.sync.aligned.m8n8.x4.trans.shared.b16 {%0,%1,%2,%3}, [%4];"
                 : "=r"(a0), "=r"(a1), "=r"(a2), "=r"(a3) : "r"(addr));
}
__device__ __forceinline__ void ldsm2t(uint32_t& r0, uint32_t& r1, uint32_t addr) {
    asm volatile("ldmatrix.sync.aligned.m8n8.x2.trans.shared.b16 {%0,%1}, [%2];"
                 : "=r"(r0), "=r"(r1) : "r"(addr));
}
__device__ __forceinline__ void mma16816(float* c, uint32_t a0, uint32_t a1,
                                         uint32_t a2, uint32_t a3,
                                         uint32_t b0, uint32_t b1) {
    asm volatile(
        "mma.sync.aligned.m16n8k16.row.col.f32.f16.f16.f32 "
        "{%0,%1,%2,%3}, {%4,%5,%6,%7}, {%8,%9}, {%0,%1,%2,%3};"
        : "+f"(c[0]), "+f"(c[1]), "+f"(c[2]), "+f"(c[3])
        : "r"(a0), "r"(a1), "r"(a2), "r"(a3), "r"(b0), "r"(b1));
}

// ---------------------------------------------------------------------------
// Kernel 1: batched SYRK via HMMA with split-fp16 inputs.
// mat=0 (G1) -> fp16 tiles in g_G16; mat=1 (G2) -> full row-major fp16 g_G2R.
// ---------------------------------------------------------------------------
#define XS_STRIDE 528
#define XS_LBASE  (128 * XS_STRIDE)
#define XS_SCR    (2 * 128 * XS_STRIDE)
#define SYRK_SMEM (XS_SCR + 64)

__global__ __launch_bounds__(256, 1) void syrk16_kernel(const float* __restrict__ U,
                                                        const float* __restrict__ A) {
    extern __shared__ unsigned char sm[];
    const uint32_t smb = smem_u32(sm);
    const int mat = blockIdx.x >> 9;
    const int b = blockIdx.x & (B_SZ - 1);
    const float* __restrict__ X = (mat ? A : U) + (size_t)b * (N_SZ * N_SZ);
    const int t = threadIdx.x;
    const int lane = t & 31;
    const int w = t >> 5;

    const uint32_t lane_tr = (uint32_t)((lane & 7) + ((lane & 16) >> 1)) * XS_STRIDE
                           + (uint32_t)(lane & 8) * 2;
    const uint32_t laneB = (uint32_t)(lane & 15) * XS_STRIDE;

    float fro = 0.f;
    float acc[5][2][4][4];
    #pragma unroll
    for (int q = 0; q < 5; q++)
        #pragma unroll
        for (int mh = 0; mh < 2; mh++)
            #pragma unroll
            for (int nq = 0; nq < 4; nq++)
                #pragma unroll
                for (int e = 0; e < 4; e++) acc[q][mh][nq][e] = 0.f;

    #pragma unroll 1
    for (int ch = 0; ch < 2; ch++) {
        if (ch) __syncthreads();
        #pragma unroll 4
        for (int idx = t; idx < 128 * 128; idx += 256) {
            const int ir = idx >> 7;
            const int jp = idx & 127;
            const float2 f = *(const float2*)(X + (size_t)(128 * ch + ir) * N_SZ + 2 * jp);
            fro = fmaf(f.x, f.x, fro);
            fro = fmaf(f.y, f.y, fro);
            const __half hx = __float2half_rn(f.x);
            const __half hy = __float2half_rn(f.y);
            const __half lx = __float2half_rn(f.x - __half2float(hx));
            const __half ly = __float2half_rn(f.y - __half2float(hy));
            *(__half2*)(sm + ir * XS_STRIDE + jp * 4) = __halves2half2(hx, hy);
            *(__half2*)(sm + XS_LBASE + ir * XS_STRIDE + jp * 4) = __halves2half2(lx, ly);
        }
        __syncthreads();

        #pragma unroll
        for (int q = 0; q < 5; q++) {
            const int tix = w + 8 * q;
            if (tix < NTILES) {
                const int a0 = c_TA[tix], b0 = c_TB[tix];
                const uint32_t acol = smb + (uint32_t)(a0 * 32) * 2 + lane_tr;
                const uint32_t bcol = smb + (uint32_t)(b0 * 32) * 2 + laneB;
                #pragma unroll
                for (int kc = 0; kc < 8; kc++) {
                    const uint32_t ro = (uint32_t)(kc * 16) * XS_STRIDE;
                    uint32_t AH[2][4], AL[2][4];
                    #pragma unroll
                    for (int mh = 0; mh < 2; mh++) {
                        const uint32_t ao = acol + ro + (uint32_t)(mh * 16) * 2;
                        ldsm4t(AH[mh][0], AH[mh][1], AH[mh][2], AH[mh][3], ao);
                        ldsm4t(AL[mh][0], AL[mh][1], AL[mh][2], AL[mh][3],
                               ao + XS_LBASE);
                    }
                    #pragma unroll
                    for (int nq = 0; nq < 4; nq++) {
                        const uint32_t bo = bcol + ro + (uint32_t)(nq * 8) * 2;
                        uint32_t bh0, bh1, bl0, bl1;
                        ldsm2t(bh0, bh1, bo);
                        ldsm2t(bl0, bl1, bo + XS_LBASE);
                        #pragma unroll
                        for (int mh = 0; mh < 2; mh++) {
                            float* c = acc[q][mh][nq];
                            mma16816(c, AH[mh][0], AH[mh][1], AH[mh][2], AH[mh][3],
                                     bh0, bh1);
                            mma16816(c, AH[mh][0], AH[mh][1], AH[mh][2], AH[mh][3],
                                     bl0, bl1);
                            mma16816(c, AL[mh][0], AL[mh][1], AL[mh][2], AL[mh][3],
                                     bh0, bh1);
                        }
                    }
                }
            }
        }
    }

    if (mat == 0) {
        // ---- G1: fp16 tile layout for pgd's ldsm preload ----
        unsigned char* gb = g_G16 + (size_t)b * MAT_BYTES;
        #pragma unroll
        for (int q = 0; q < 5; q++) {
            const int tix = w + 8 * q;
            if (tix < NTILES) {
                #pragma unroll
                for (int mh = 0; mh < 2; mh++)
                    #pragma unroll
                    for (int nq = 0; nq < 4; nq++) {
                        const float* c = acc[q][mh][nq];
                        const uint32_t o = (uint32_t)tix * TILE_BYTES
                            + (uint32_t)(mh * 16 + (lane >> 2)) * TILE_STRIDE_B
                            + (uint32_t)(nq * 4 + (lane & 3)) * 4;
                        *(__half2*)(gb + o) =
                            __halves2half2(__float2half_rn(c[0]), __float2half_rn(c[1]));
                        *(__half2*)(gb + o + 8 * TILE_STRIDE_B) =
                            __halves2half2(__float2half_rn(c[2]), __float2half_rn(c[3]));
                    }
            }
        }
    } else {
        // ---- G2: full row-major fp16 ----
        unsigned short* g2 = g_G2R + (size_t)b * (N_SZ * N_SZ);
        #pragma unroll
        for (int q = 0; q < 5; q++) {
            const int tix = w + 8 * q;
            if (tix < NTILES) {
                const int a0 = c_TA[tix], b0 = c_TB[tix];
                #pragma unroll
                for (int mh = 0; mh < 2; mh++)
                    #pragma unroll
                    for (int nq = 0; nq < 4; nq++) {
                        const float* c = acc[q][mh][nq];
                        const int row = a0 * 32 + mh * 16 + (lane >> 2);
                        const int col = b0 * 32 + nq * 8 + (lane & 3) * 2;
                        const __half h0 = __float2half_rn(c[0]);
                        const __half h1 = __float2half_rn(c[1]);
                        const __half h2 = __float2half_rn(c[2]);
                        const __half h3 = __float2half_rn(c[3]);
                        *(__half2*)(g2 + (size_t)row * N_SZ + col) = __halves2half2(h0, h1);
                        *(__half2*)(g2 + (size_t)(row + 8) * N_SZ + col) = __halves2half2(h2, h3);
                        if (a0 != b0) {
                            g2[(size_t)col * N_SZ + row] = __half_as_ushort(h0);
                            g2[(size_t)(col + 1) * N_SZ + row] = __half_as_ushort(h1);
                            g2[(size_t)col * N_SZ + row + 8] = __half_as_ushort(h2);
                            g2[(size_t)(col + 1) * N_SZ + row + 8] = __half_as_ushort(h3);
                        }
                    }
            }
        }
    }

    #pragma unroll
    for (int o = 16; o; o >>= 1) fro += __shfl_xor_sync(0xFFFFFFFFu, fro, o);
    float* scr = (float*)(sm + XS_SCR);
    if (lane == 0) scr[w] = fro;
    __syncthreads();
    if (t == 0) {
        float s = 0.f;
        #pragma unroll
        for (int qq = 0; qq < 8; qq++) s += scr[qq];
        g_fro[mat * B_SZ + b] = s;
    }
}

// ---------------------------------------------------------------------------
// Kernel 2: 400-iteration PGD. 256 threads = 8 warps.
//   G1: HMMA, ALL 8 k-bands register-resident (128 frag regs), b-frags from
//       warp-private packed-w (ld.shared.v2). Zero in-loop LDSM.
//   G2: scalar HFMA2, thread t owns row t; G2 full rows fp16 in smem
//       (528B padded stride, bandwidth-floor conflicts); w broadcast half2;
//       fp16 accumulators (R12-validated for the kappa-scaled G2 term).
// Smem phase overlap: G1 tiles staged at [0,92KB) only for the ldsm preload,
// then overwritten by G2 rows. One __syncthreads per iteration.
// ---------------------------------------------------------------------------
#define G2_ROW_B  528                           // 256 halves + 8 pad
#define SM_G2     0                             // 256*528 = 135168
#define SM_WPK    135168                        // 8 warps x 512B packed w
#define SM_WH     139264                        // 8 warps x 512B plain half w
#define SM_Y1     143360                        // [2][256] f32 transposed
#define SM_Y2     145408
#define SM_PROD   147456                        // [2][8] f32
#define SM_TOTAL  147584

__global__ __launch_bounds__(256, 1) void pgd_mma_kernel(const float* __restrict__ mu,
                                                         float* __restrict__ out) {
    extern __shared__ unsigned char sm[];
    const uint32_t smb = smem_u32(sm);
    const int b = blockIdx.x;
    const int t = threadIdx.x;
    const int lane = t & 31;
    const int r = t >> 5;                   // warp id == output band

    // ---- Phase A: stage G1 tiles at [0, 92160) ----
    {
        const uint4* src = (const uint4*)(g_G16 + (size_t)b * MAT_BYTES);
        uint4* dst = (uint4*)sm;
        #pragma unroll 4
        for (int i = t; i < MAT_BYTES / 16; i += 256) dst[i] = src[i];
    }
    __syncthreads();

    const uint32_t lane_nt = (uint32_t)((lane & 7) + (lane & 8)) * TILE_STRIDE_B
                           + (uint32_t)((lane & 16) >> 1) * 2;
    const uint32_t lane_tr = (uint32_t)((lane & 7) + ((lane & 16) >> 1)) * TILE_STRIDE_B
                           + (uint32_t)(lane & 8) * 2;

    // ---- preload ALL 8 G1 k-bands into registers (128 frag regs) ----
    uint32_t fr[8][2][2][4];
    #pragma unroll
    for (int bb = 0; bb < 8; bb++) {
        const bool trp = (bb < r);
        const int aa = trp ? bb : r;
        const int bn = trp ? r : bb;
        const uint32_t tile = smb + (uint32_t)tri_idx(aa, bn) * TILE_BYTES;
        #pragma unroll
        for (int ks = 0; ks < 2; ks++) {
            if (trp) {
                const uint32_t o = (uint32_t)ks * (16 * TILE_STRIDE_B) + lane_tr;
                ldsm4t(fr[bb][ks][0][0], fr[bb][ks][0][1],
                       fr[bb][ks][0][2], fr[bb][ks][0][3], tile + o);
                ldsm4t(fr[bb][ks][1][0], fr[bb][ks][1][1],
                       fr[bb][ks][1][2], fr[bb][ks][1][3], tile + o + 32);
            } else {
                const uint32_t o = (uint32_t)ks * 32 + lane_nt;
                ldsm4(fr[bb][ks][0][0], fr[bb][ks][0][1],
                      fr[bb][ks][0][2], fr[bb][ks][0][3], tile + o);
                ldsm4(fr[bb][ks][1][0], fr[bb][ks][1][1],
                      fr[bb][ks][1][2], fr[bb][ks][1][3],
                      tile + o + 16 * TILE_STRIDE_B);
            }
        }
    }
    __syncthreads();   // all warps done reading tiles

    // ---- Phase B: G2 rows into [0, 135168), padded stride 528B ----
    {
        const unsigned char* src = (const unsigned char*)(g_G2R + (size_t)b * (N_SZ * N_SZ));
        #pragma unroll 4
        for (int c = t; c < 8192; c += 256) {
            const int row = c >> 5;
            const int intra = c & 31;
            *(uint4*)(sm + SM_G2 + row * G2_ROW_B + intra * 16) =
                *(const uint4*)(src + (size_t)c * 16);
        }
    }

    const uint32_t wpk = smb + SM_WPK + (uint32_t)r * 512;
    const uint32_t whb = smb + SM_WH + (uint32_t)r * 512;
    const uint32_t g2row = smb + SM_G2 + (uint32_t)t * G2_ROW_B;

    // packed-w writer offset (R12 layout, validated)
    const int pw = lane & 15;
    const uint32_t lane_woff = (uint32_t)(((lane >> 4) & 1) * 4 + ((pw >> 1) & 3)) * 8
                             + (uint32_t)((((pw >> 3) << 1) | (pw & 1)) * 2);

    const float step = 1.0f / (LAMBD * g_fro[b] + KAPPA * sqrtf(g_fro[B_SZ + b]) + 1.0f);

    // ---- replicated solver state (identical in every warp) ----
    float wv[8], mu_r[8];
    float tau = 0.0f;
    #pragma unroll
    for (int k = 0; k < 8; k++) {
        wv[k] = 1.0f / (float)N_SZ;
        mu_r[k] = mu[(size_t)b * N_SZ + lane + (k << 5)];
        const __half h = __float2half_rn(wv[k]);
        asm volatile("st.shared.u16 [%0], %1;"
                     :: "r"(wpk + (uint32_t)k * 64 + lane_woff),
                        "h"(__half_as_ushort(h)) : "memory");
        asm volatile("st.shared.u16 [%0], %1;"
                     :: "r"(whb + (uint32_t)(lane + (k << 5)) * 2),
                        "h"(__half_as_ushort(h)) : "memory");
    }
    __syncwarp();
    __syncthreads();

    #pragma unroll 1
    for (int it = 0; it < N_ITERS; it++) {
        const uint32_t buf = (uint32_t)(it & 1);
        float* const y1s = (float*)(sm + SM_Y1 + buf * 1024);
        float* const y2s = (float*)(sm + SM_Y2 + buf * 1024);
        float* const prods = (float*)(sm + SM_PROD + buf * 32);

        // ---- G1 matvec: 32 HMMA, all operands in registers ----
        float cA[4] = {0.f,0.f,0.f,0.f}, cB[4] = {0.f,0.f,0.f,0.f};
        #pragma unroll
        for (int bb = 0; bb < 8; bb++) {
            #pragma unroll
            for (int ks = 0; ks < 2; ks++) {
                uint32_t b0, b1;
                const uint32_t waddr = wpk + (uint32_t)((bb * 8 + ks * 4) * 8)
                                     + (uint32_t)(lane & 3) * 8;
                asm volatile("ld.shared.v2.b32 {%0,%1}, [%2];"
                             : "=r"(b0), "=r"(b1) : "r"(waddr));
                if (lane >= 4) { b0 = 0u; b1 = 0u; }
                mma16816(cA, fr[bb][ks][0][0], fr[bb][ks][0][1],
                             fr[bb][ks][0][2], fr[bb][ks][0][3], b0, b1);
                mma16816(cB, fr[bb][ks][1][0], fr[bb][ks][1][1],
                             fr[bb][ks][1][2], fr[bb][ks][1][3], b0, b1);
            }
        }

        // ---- G2 matvec: row t dot w, HFMA2 with fp16 accumulators ----
        __half2 a2[8];
        #pragma unroll
        for (int q = 0; q < 8; q++) a2[q] = __halves2half2(__ushort_as_half(0),
                                                           __ushort_as_half(0));
        #pragma unroll
        for (int c = 0; c < 32; c++) {
            const uint4 gv = *(const uint4*)(sm + SM_G2 + (g2row - smb - SM_G2) + c * 16);
            const uint4 wq = *(const uint4*)(sm + SM_WH + (uint32_t)r * 512 + c * 16);
            const int q = (c & 1) * 4;
            a2[q + 0] = __hfma2(*(const __half2*)&gv.x, *(const __half2*)&wq.x, a2[q + 0]);
            a2[q + 1] = __hfma2(*(const __half2*)&gv.y, *(const __half2*)&wq.y, a2[q + 1]);
            a2[q + 2] = __hfma2(*(const __half2*)&gv.z, *(const __half2*)&wq.z, a2[q + 2]);
            a2[q + 3] = __hfma2(*(const __half2*)&gv.w, *(const __half2*)&wq.w, a2[q + 3]);
        }
        float y2 = 0.f;
        #pragma unroll
        for (int q = 0; q < 8; q++)
            y2 += __low2float(a2[q]) + __high2float(a2[q]);

        // ---- publish y bands (transposed layout) ----
        const int g = lane >> 2;
        if ((lane & 3) == 0) {
            y1s[g * 8 + r]        = cA[0];
            y1s[(g + 8) * 8 + r]  = cA[2];
            y1s[(g + 16) * 8 + r] = cB[0];
            y1s[(g + 24) * 8 + r] = cB[2];
        }
        y2s[lane * 8 + r] = y2;     // thread t owns row t = 32r+lane

        // ---- w.(G2 w) partial for this warp's 32 rows ----
        {
            float p = wv[r] * y2;
            p += __shfl_xor_sync(0xFFFFFFFFu, p, 1);
            p += __shfl_xor_sync(0xFFFFFFFFu, p, 2);
            p += __shfl_xor_sync(0xFFFFFFFFu, p, 4);
            p += __shfl_xor_sync(0xFFFFFFFFu, p, 8);
            p += __shfl_xor_sync(0xFFFFFFFFu, p, 16);
            if (lane == 0) prods[r] = p;
        }
        __syncthreads();   // the ONLY barrier per iteration

        // ---- replicated projection (vectorized reads) ----
        float4 pv0 = *(const float4*)prods;
        float4 pv1 = *(const float4*)(prods + 4);
        const float pr = ((pv0.x + pv0.y) + (pv0.z + pv0.w))
                       + ((pv1.x + pv1.y) + (pv1.z + pv1.w));
        const float nrm = sqrtf(fmaxf(pr, 1e-12f));
        const float kin = KAPPA / nrm;

        float v[8];
        {
            const float4 a0 = *(const float4*)(y1s + lane * 8);
            const float4 a1 = *(const float4*)(y1s + lane * 8 + 4);
            const float4 b0v = *(const float4*)(y2s + lane * 8);
            const float4 b1v = *(const float4*)(y2s + lane * 8 + 4);
            v[0] = wv[0] - step * (-mu_r[0] + LAMBD * a0.x + kin * b0v.x);
            v[1] = wv[1] - step * (-mu_r[1] + LAMBD * a0.y + kin * b0v.y);
            v[2] = wv[2] - step * (-mu_r[2] + LAMBD * a0.z + kin * b0v.z);
            v[3] = wv[3] - step * (-mu_r[3] + LAMBD * a0.w + kin * b0v.w);
            v[4] = wv[4] - step * (-mu_r[4] + LAMBD * a1.x + kin * b1v.x);
            v[5] = wv[5] - step * (-mu_r[5] + LAMBD * a1.y + kin * b1v.y);
            v[6] = wv[6] - step * (-mu_r[6] + LAMBD * a1.z + kin * b1v.z);
            v[7] = wv[7] - step * (-mu_r[7] + LAMBD * a1.w + kin * b1v.w);
        }

        // Warm-started Newton on f(tau) = sum(relu(v-tau)) - 1.
        float tt = tau;
        bool fb = false;
        for (int ni = 0; ni < 12; ni++) {
            float s = 0.f;
            int cnt = 0;
            #pragma unroll
            for (int k = 0; k < 8; k++) {
                const float d = v[k] - tt;
                if (d > 0.f) { s += d; cnt++; }
            }
            cnt = __reduce_add_sync(0xFFFFFFFFu, cnt);
            #pragma unroll
            for (int o = 16; o; o >>= 1)
                s += __shfl_xor_sync(0xFFFFFFFFu, s, o);
            if (cnt == 0) {
                if (fb) break;
                fb = true;
                float S = 0.f;
                #pragma unroll
                for (int k = 0; k < 8; k++) S += v[k];
                #pragma unroll
                for (int o = 16; o; o >>= 1)
                    S += __shfl_xor_sync(0xFFFFFFFFu, S, o);
                tt = (S - 1.0f) * (1.0f / (float)N_SZ);
                continue;
            }
            const float delta = (s - 1.0f) / (float)cnt;
            tt += delta;
            if (fabsf(delta) <= 1e-10f) break;
        }
        tau = tt;

        #pragma unroll
        for (int k = 0; k < 8; k++) {
            wv[k] = fmaxf(v[k] - tau, 0.f);
            const __half h = __float2half_rn(wv[k]);
            asm volatile("st.shared.u16 [%0], %1;"
                         :: "r"(wpk + (uint32_t)k * 64 + lane_woff),
                            "h"(__half_as_ushort(h)) : "memory");
            asm volatile("st.shared.u16 [%0], %1;"
                         :: "r"(whb + (uint32_t)(lane + (k << 5)) * 2),
                            "h"(__half_as_ushort(h)) : "memory");
        }
        __syncwarp();
    }

    // ---- final clamp + renormalize (warp 0 writes) ----
    if (r == 0) {
        float s = 0.f;
        #pragma unroll
        for (int k = 0; k < 8; k++) { wv[k] = fmaxf(wv[k], 0.f); s += wv[k]; }
        #pragma unroll
        for (int o = 16; o; o >>= 1) s += __shfl_xor_sync(0xFFFFFFFFu, s, o);
        const float inv = 1.0f / (s + 1e-12f);
        #pragma unroll
        for (int k = 0; k < 8; k++)
            out[(size_t)b * N_SZ + lane + (k << 5)] = wv[k] * inv;
    }
}

// ---------------------------------------------------------------------------
// Launcher
// ---------------------------------------------------------------------------
extern "C" void kernel_launch(void* const* d_in, const int* in_sizes, int n_in,
                              void* d_out, int out_size) {
    const float* mu = (const float*)d_in[0];
    const float* U  = (const float*)d_in[1];
    const float* A  = (const float*)d_in[2];
    float* out = (float*)d_out;

    cudaFuncSetAttribute(syrk16_kernel, cudaFuncAttributeMaxDynamicSharedMemorySize,
                         SYRK_SMEM);
    cudaFuncSetAttribute(pgd_mma_kernel, cudaFuncAttributeMaxDynamicSharedMemorySize,
                         SM_TOTAL);

    syrk16_kernel<<<2 * B_SZ, 256, SYRK_SMEM>>>(U, A);
    pgd_mma_kernel<<<B_SZ, 256, SM_TOTAL>>>(mu, out);
}

// round 15
// speedup vs baseline: 1.6453x; 1.1443x over previous
#include <cuda_runtime.h>
#include <cuda_fp16.h>
#include <math.h>
#include <stdint.h>

// Problem constants
#define B_SZ    512
#define N_SZ    256
#define N_ITERS 400
#define LAMBD   1.0f
#define KAPPA   0.1f

// 32x32 tiles over the 8x8 tile-grid upper triangle: 36 tiles per matrix.
#define NTILES 36
__constant__ int c_TA[NTILES] = {0,0,0,0,0,0,0,0, 1,1,1,1,1,1,1, 2,2,2,2,2,2,
                                 3,3,3,3,3, 4,4,4,4, 5,5,5, 6,6, 7};
__constant__ int c_TB[NTILES] = {0,1,2,3,4,5,6,7, 1,2,3,4,5,6,7, 2,3,4,5,6,7,
                                 3,4,5,6,7, 4,5,6,7, 5,6,7, 6,7, 7};

__device__ __forceinline__ int tri_idx(int a, int b) {  // a <= b
    return a * 8 - (a * (a - 1)) / 2 + (b - a);
}

// fp16 G tile store: 32 rows x 40 halves (80B stride)
#define TILE_STRIDE_B 80
#define TILE_BYTES    (32 * TILE_STRIDE_B)      // 2560
#define MAT_BYTES     (NTILES * TILE_BYTES)     // 92160
#define BATCH_BYTES   (2 * MAT_BYTES)           // 184320

__device__ unsigned char g_G16[(size_t)B_SZ * BATCH_BYTES];  // ~94 MB
__device__ float g_fro[2 * B_SZ];

// ---------------------------------------------------------------------------
// PTX helpers (base PTX only; no 'a'-gated instructions)
// ---------------------------------------------------------------------------
__device__ __forceinline__ uint32_t smem_u32(const void* p) {
    uint32_t a;
    asm("{ .reg .u64 t; cvta.to.shared.u64 t, %1; cvt.u32.u64 %0, t; }"
        : "=r"(a) : "l"(p));
    return a;
}
__device__ __forceinline__ void ldsm4(uint32_t& a0, uint32_t& a1, uint32_t& a2,
                                      uint32_t& a3, uint32_t addr) {
    asm volatile("ldmatrix.sync.aligned.m8n8.x4.shared.b16 {%0,%1,%2,%3}, [%4];"
                 : "=r"(a0), "=r"(a1), "=r"(a2), "=r"(a3) : "r"(addr));
}
__device__ __forceinline__ void ldsm4t(uint32_t& a0, uint32_t& a1, uint32_t& a2,
                                       uint32_t& a3, uint32_t addr) {
    asm volatile("ldmatrix.sync.aligned.m8n8.x4.trans.shared.b16 {%0,%1,%2,%3}, [%4];"
                 : "=r"(a0), "=r"(a1), "=r"(a2), "=r"(a3) : "r"(addr));
}
__device__ __forceinline__ void ldsm2t(uint32_t& r0, uint32_t& r1, uint32_t addr) {
    asm volatile("ldmatrix.sync.aligned.m8n8.x2.trans.shared.b16 {%0,%1}, [%2];"
                 : "=r"(r0), "=r"(r1) : "r"(addr));
}
__device__ __forceinline__ void mma16816(float* c, uint32_t a0, uint32_t a1,
                                         uint32_t a2, uint32_t a3,
                                         uint32_t b0, uint32_t b1) {
    asm volatile(
        "mma.sync.aligned.m16n8k16.row.col.f32.f16.f16.f32 "
        "{%0,%1,%2,%3}, {%4,%5,%6,%7}, {%8,%9}, {%0,%1,%2,%3};"
        : "+f"(c[0]), "+f"(c[1]), "+f"(c[2]), "+f"(c[3])
        : "r"(a0), "r"(a1), "r"(a2), "r"(a3), "r"(b0), "r"(b1));
}
__device__ __forceinline__ void mma16816h(uint32_t* c, uint32_t a0, uint32_t a1,
                                          uint32_t a2, uint32_t a3,
                                          uint32_t b0, uint32_t b1) {
    asm volatile(
        "mma.sync.aligned.m16n8k16.row.col.f16.f16.f16.f16 "
        "{%0,%1}, {%2,%3,%4,%5}, {%6,%7}, {%0,%1};"
        : "+r"(c[0]), "+r"(c[1])
        : "r"(a0), "r"(a1), "r"(a2), "r"(a3), "r"(b0), "r"(b1));
}

// ---------------------------------------------------------------------------
// Kernel 1: batched SYRK via HMMA with split-fp16 inputs (unchanged from R8).
// ---------------------------------------------------------------------------
#define XS_STRIDE 528
#define XS_LBASE  (128 * XS_STRIDE)
#define XS_SCR    (2 * 128 * XS_STRIDE)
#define SYRK_SMEM (XS_SCR + 64)

__global__ __launch_bounds__(256, 1) void syrk16_kernel(const float* __restrict__ U,
                                                        const float* __restrict__ A) {
    extern __shared__ unsigned char sm[];
    const uint32_t smb = smem_u32(sm);
    const int mat = blockIdx.x >> 9;
    const int b = blockIdx.x & (B_SZ - 1);
    const float* __restrict__ X = (mat ? A : U) + (size_t)b * (N_SZ * N_SZ);
    const int t = threadIdx.x;
    const int lane = t & 31;
    const int w = t >> 5;

    const uint32_t lane_tr = (uint32_t)((lane & 7) + ((lane & 16) >> 1)) * XS_STRIDE
                           + (uint32_t)(lane & 8) * 2;
    const uint32_t laneB = (uint32_t)(lane & 15) * XS_STRIDE;

    float fro = 0.f;
    float acc[5][2][4][4];
    #pragma unroll
    for (int q = 0; q < 5; q++)
        #pragma unroll
        for (int mh = 0; mh < 2; mh++)
            #pragma unroll
            for (int nq = 0; nq < 4; nq++)
                #pragma unroll
                for (int e = 0; e < 4; e++) acc[q][mh][nq][e] = 0.f;

    #pragma unroll 1
    for (int ch = 0; ch < 2; ch++) {
        if (ch) __syncthreads();
        #pragma unroll 4
        for (int idx = t; idx < 128 * 128; idx += 256) {
            const int ir = idx >> 7;
            const int jp = idx & 127;
            const float2 f = *(const float2*)(X + (size_t)(128 * ch + ir) * N_SZ + 2 * jp);
            fro = fmaf(f.x, f.x, fro);
            fro = fmaf(f.y, f.y, fro);
            const __half hx = __float2half_rn(f.x);
            const __half hy = __float2half_rn(f.y);
            const __half lx = __float2half_rn(f.x - __half2float(hx));
            const __half ly = __float2half_rn(f.y - __half2float(hy));
            *(__half2*)(sm + ir * XS_STRIDE + jp * 4) = __halves2half2(hx, hy);
            *(__half2*)(sm + XS_LBASE + ir * XS_STRIDE + jp * 4) = __halves2half2(lx, ly);
        }
        __syncthreads();

        #pragma unroll
        for (int q = 0; q < 5; q++) {
            const int tix = w + 8 * q;
            if (tix < NTILES) {
                const int a0 = c_TA[tix], b0 = c_TB[tix];
                const uint32_t acol = smb + (uint32_t)(a0 * 32) * 2 + lane_tr;
                const uint32_t bcol = smb + (uint32_t)(b0 * 32) * 2 + laneB;
                #pragma unroll
                for (int kc = 0; kc < 8; kc++) {
                    const uint32_t ro = (uint32_t)(kc * 16) * XS_STRIDE;
                    uint32_t AH[2][4], AL[2][4];
                    #pragma unroll
                    for (int mh = 0; mh < 2; mh++) {
                        const uint32_t ao = acol + ro + (uint32_t)(mh * 16) * 2;
                        ldsm4t(AH[mh][0], AH[mh][1], AH[mh][2], AH[mh][3], ao);
                        ldsm4t(AL[mh][0], AL[mh][1], AL[mh][2], AL[mh][3],
                               ao + XS_LBASE);
                    }
                    #pragma unroll
                    for (int nq = 0; nq < 4; nq++) {
                        const uint32_t bo = bcol + ro + (uint32_t)(nq * 8) * 2;
                        uint32_t bh0, bh1, bl0, bl1;
                        ldsm2t(bh0, bh1, bo);
                        ldsm2t(bl0, bl1, bo + XS_LBASE);
                        #pragma unroll
                        for (int mh = 0; mh < 2; mh++) {
                            float* c = acc[q][mh][nq];
                            mma16816(c, AH[mh][0], AH[mh][1], AH[mh][2], AH[mh][3],
                                     bh0, bh1);
                            mma16816(c, AH[mh][0], AH[mh][1], AH[mh][2], AH[mh][3],
                                     bl0, bl1);
                            mma16816(c, AL[mh][0], AL[mh][1], AL[mh][2], AL[mh][3],
                                     bh0, bh1);
                        }
                    }
                }
            }
        }
    }

    unsigned char* gb = g_G16 + (size_t)b * BATCH_BYTES + (size_t)mat * MAT_BYTES;
    #pragma unroll
    for (int q = 0; q < 5; q++) {
        const int tix = w + 8 * q;
        if (tix < NTILES) {
            #pragma unroll
            for (int mh = 0; mh < 2; mh++)
                #pragma unroll
                for (int nq = 0; nq < 4; nq++) {
                    const float* c = acc[q][mh][nq];
                    const uint32_t o = (uint32_t)tix * TILE_BYTES
                        + (uint32_t)(mh * 16 + (lane >> 2)) * TILE_STRIDE_B
                        + (uint32_t)(nq * 4 + (lane & 3)) * 4;
                    *(__half2*)(gb + o) =
                        __halves2half2(__float2half_rn(c[0]), __float2half_rn(c[1]));
                    *(__half2*)(gb + o + 8 * TILE_STRIDE_B) =
                        __halves2half2(__float2half_rn(c[2]), __float2half_rn(c[3]));
                }
        }
    }

    #pragma unroll
    for (int o = 16; o; o >>= 1) fro += __shfl_xor_sync(0xFFFFFFFFu, fro, o);
    float* scr = (float*)(sm + XS_SCR);
    if (lane == 0) scr[w] = fro;
    __syncthreads();
    if (t == 0) {
        float s = 0.f;
        #pragma unroll
        for (int qq = 0; qq < 8; qq++) s += scr[qq];
        g_fro[mat * B_SZ + b] = s;
    }
}

// ---------------------------------------------------------------------------
// Kernel 2: 400-iteration PGD (R12 champion + latency cuts).
//   - streamed bands FIRST (LDSM latency hidden under reg-band MMAs)
//   - no b-frag zeroing (cols 1..7 of D valid-but-unused)
//   - kin via rsqrt; Newton cap 8
// ---------------------------------------------------------------------------
#define SM_WPRIV 0                               // 8 warps x 512 B packed w
#define SM_Y1    4096                            // [2][256] f32 transposed
#define SM_Y2    6144
#define SM_PROD  8192
#define SM_TILES 10240
#define SM_TOTAL (SM_TILES + BATCH_BYTES)        // 194560

__global__ __launch_bounds__(256, 1) void pgd_mma_kernel(const float* __restrict__ mu,
                                                         float* __restrict__ out) {
    extern __shared__ unsigned char sm[];
    const uint32_t smb = smem_u32(sm);
    const int b = blockIdx.x;
    const int t = threadIdx.x;
    const int lane = t & 31;
    const int r = t >> 5;                   // warp id == output band

    // ---- init: raw copy of both fp16 triangles ----
    {
        const uint4* src = (const uint4*)(g_G16 + (size_t)b * BATCH_BYTES);
        uint4* dst = (uint4*)(sm + SM_TILES);
        #pragma unroll 4
        for (int i = t; i < BATCH_BYTES / 16; i += 256) dst[i] = src[i];
    }

    const uint32_t t1base = smb + SM_TILES;
    const uint32_t t2base = smb + SM_TILES + MAT_BYTES;
    const uint32_t wpriv = smb + SM_WPRIV + (uint32_t)r * 512;

    const uint32_t lane_nt = (uint32_t)((lane & 7) + (lane & 8)) * TILE_STRIDE_B
                           + (uint32_t)((lane & 16) >> 1) * 2;
    const uint32_t lane_tr = (uint32_t)((lane & 7) + ((lane & 16) >> 1)) * TILE_STRIDE_B
                           + (uint32_t)(lane & 8) * 2;

    // packed-w writer offset (R12 layout, validated)
    const int pw = lane & 15;
    const uint32_t lane_woff = (uint32_t)(((lane >> 4) & 1) * 4 + ((pw >> 1) & 3)) * 8
                             + (uint32_t)((((pw >> 3) << 1) | (pw & 1)) * 2);

    const float step = 1.0f / (LAMBD * g_fro[b] + KAPPA * sqrtf(g_fro[B_SZ + b]) + 1.0f);

    __syncthreads();

    // ---- preload k-bands 0..4 into registers (160 frag regs) ----
    uint32_t fr[2][5][2][2][4];
    #pragma unroll
    for (int m = 0; m < 2; m++) {
        const uint32_t tb = m ? t2base : t1base;
        #pragma unroll
        for (int bb = 0; bb < 5; bb++) {
            const bool trp = (bb < r);
            const int aa = trp ? bb : r;
            const int bn = trp ? r : bb;
            const uint32_t tile = tb + (uint32_t)tri_idx(aa, bn) * TILE_BYTES;
            #pragma unroll
            for (int ks = 0; ks < 2; ks++) {
                if (trp) {
                    const uint32_t o = (uint32_t)ks * (16 * TILE_STRIDE_B) + lane_tr;
                    ldsm4t(fr[m][bb][ks][0][0], fr[m][bb][ks][0][1],
                           fr[m][bb][ks][0][2], fr[m][bb][ks][0][3], tile + o);
                    ldsm4t(fr[m][bb][ks][1][0], fr[m][bb][ks][1][1],
                           fr[m][bb][ks][1][2], fr[m][bb][ks][1][3], tile + o + 32);
                } else {
                    const uint32_t o = (uint32_t)ks * 32 + lane_nt;
                    ldsm4(fr[m][bb][ks][0][0], fr[m][bb][ks][0][1],
                          fr[m][bb][ks][0][2], fr[m][bb][ks][0][3], tile + o);
                    ldsm4(fr[m][bb][ks][1][0], fr[m][bb][ks][1][1],
                          fr[m][bb][ks][1][2], fr[m][bb][ks][1][3],
                          tile + o + 16 * TILE_STRIDE_B);
                }
            }
        }
    }

    // ---- replicated solver state (identical in every warp) ----
    float wv[8], mu_r[8];
    float tau = 0.0f;
    #pragma unroll
    for (int k = 0; k < 8; k++) {
        wv[k] = 1.0f / (float)N_SZ;
        mu_r[k] = mu[(size_t)b * N_SZ + lane + (k << 5)];
        const __half h = __float2half_rn(wv[k]);
        asm volatile("st.shared.u16 [%0], %1;"
                     :: "r"(wpriv + (uint32_t)k * 64 + lane_woff),
                        "h"(__half_as_ushort(h)) : "memory");
    }
    __syncwarp();
    __syncthreads();

    #pragma unroll 1
    for (int it = 0; it < N_ITERS; it++) {
        const uint32_t buf = (uint32_t)(it & 1);
        float* const y1s = (float*)(sm + SM_Y1 + buf * 1024);
        float* const y2s = (float*)(sm + SM_Y2 + buf * 1024);
        float* const prods = (float*)(sm + SM_PROD + buf * 32);

        float c1A[4] = {0.f,0.f,0.f,0.f}, c1B[4] = {0.f,0.f,0.f,0.f};
        uint32_t h2A[2] = {0u, 0u}, h2B[2] = {0u, 0u};   // G2 fp16 accumulators

        // ---- STREAMED k-bands 5..7 FIRST: LDSM issued early, latency hidden
        // behind the register-band MMAs that follow.
        #pragma unroll
        for (int bb = 5; bb < 8; bb++) {
            const bool trp = (bb < r);
            const int aa = trp ? bb : r;
            const int bn = trp ? r : bb;
            const uint32_t toff = (uint32_t)tri_idx(aa, bn) * TILE_BYTES;
            const uint32_t tile1 = t1base + toff;
            const uint32_t tile2 = t2base + toff;
            #pragma unroll
            for (int ks = 0; ks < 2; ks++) {
                uint32_t b0, b1;
                const uint32_t waddr = wpriv + (uint32_t)((bb * 8 + ks * 4) * 8)
                                     + (uint32_t)(lane & 3) * 8;
                asm volatile("ld.shared.v2.b32 {%0,%1}, [%2];"
                             : "=r"(b0), "=r"(b1) : "r"(waddr));

                uint32_t sA[4][4];
                if (trp) {
                    const uint32_t o = (uint32_t)ks * (16 * TILE_STRIDE_B) + lane_tr;
                    ldsm4t(sA[0][0], sA[0][1], sA[0][2], sA[0][3], tile1 + o);
                    ldsm4t(sA[1][0], sA[1][1], sA[1][2], sA[1][3], tile1 + o + 32);
                    ldsm4t(sA[2][0], sA[2][1], sA[2][2], sA[2][3], tile2 + o);
                    ldsm4t(sA[3][0], sA[3][1], sA[3][2], sA[3][3], tile2 + o + 32);
                } else {
                    const uint32_t o = (uint32_t)ks * 32 + lane_nt;
                    ldsm4(sA[0][0], sA[0][1], sA[0][2], sA[0][3], tile1 + o);
                    ldsm4(sA[1][0], sA[1][1], sA[1][2], sA[1][3],
                          tile1 + o + 16 * TILE_STRIDE_B);
                    ldsm4(sA[2][0], sA[2][1], sA[2][2], sA[2][3], tile2 + o);
                    ldsm4(sA[3][0], sA[3][1], sA[3][2], sA[3][3],
                          tile2 + o + 16 * TILE_STRIDE_B);
                }
                mma16816(c1A, sA[0][0], sA[0][1], sA[0][2], sA[0][3], b0, b1);
                mma16816(c1B, sA[1][0], sA[1][1], sA[1][2], sA[1][3], b0, b1);
                mma16816h(h2A, sA[2][0], sA[2][1], sA[2][2], sA[2][3], b0, b1);
                mma16816h(h2B, sA[3][0], sA[3][1], sA[3][2], sA[3][3], b0, b1);
            }
        }

        // ---- register-resident k-bands 0..4 ----
        #pragma unroll
        for (int bb = 0; bb < 5; bb++) {
            #pragma unroll
            for (int ks = 0; ks < 2; ks++) {
                uint32_t b0, b1;
                const uint32_t waddr = wpriv + (uint32_t)((bb * 8 + ks * 4) * 8)
                                     + (uint32_t)(lane & 3) * 8;
                asm volatile("ld.shared.v2.b32 {%0,%1}, [%2];"
                             : "=r"(b0), "=r"(b1) : "r"(waddr));

                mma16816(c1A, fr[0][bb][ks][0][0], fr[0][bb][ks][0][1],
                              fr[0][bb][ks][0][2], fr[0][bb][ks][0][3], b0, b1);
                mma16816(c1B, fr[0][bb][ks][1][0], fr[0][bb][ks][1][1],
                              fr[0][bb][ks][1][2], fr[0][bb][ks][1][3], b0, b1);
                mma16816h(h2A, fr[1][bb][ks][0][0], fr[1][bb][ks][0][1],
                               fr[1][bb][ks][0][2], fr[1][bb][ks][0][3], b0, b1);
                mma16816h(h2B, fr[1][bb][ks][1][0], fr[1][bb][ks][1][1],
                               fr[1][bb][ks][1][2], fr[1][bb][ks][1][3], b0, b1);
            }
        }

        // ---- extract G2 results (col 0 = low half of each f16x2 pair) ----
        const float c2A0 = __low2float(*(const __half2*)&h2A[0]);
        const float c2A2 = __low2float(*(const __half2*)&h2A[1]);
        const float c2B0 = __low2float(*(const __half2*)&h2B[0]);
        const float c2B2 = __low2float(*(const __half2*)&h2B[1]);

        // ---- store y bands TRANSPOSED: y[c] -> float idx (c&31)*8 + (c>>5)
        const int g = lane >> 2;
        if ((lane & 3) == 0) {
            y1s[g * 8 + r]        = c1A[0];
            y1s[(g + 8) * 8 + r]  = c1A[2];
            y1s[(g + 16) * 8 + r] = c1B[0];
            y1s[(g + 24) * 8 + r] = c1B[2];
            y2s[g * 8 + r]        = c2A0;
            y2s[(g + 8) * 8 + r]  = c2A2;
            y2s[(g + 16) * 8 + r] = c2B0;
            y2s[(g + 24) * 8 + r] = c2B2;
        }
        {
            const float wg0 = __shfl_sync(0xFFFFFFFFu, wv[r], g);
            const float wg1 = __shfl_sync(0xFFFFFFFFu, wv[r], g + 8);
            const float wg2 = __shfl_sync(0xFFFFFFFFu, wv[r], g + 16);
            const float wg3 = __shfl_sync(0xFFFFFFFFu, wv[r], g + 24);
            float p = c2A0 * wg0 + c2A2 * wg1 + c2B0 * wg2 + c2B2 * wg3;
            p += __shfl_xor_sync(0xFFFFFFFFu, p, 4);
            p += __shfl_xor_sync(0xFFFFFFFFu, p, 8);
            p += __shfl_xor_sync(0xFFFFFFFFu, p, 16);
            if (lane == 0) prods[r] = p;
        }
        __syncthreads();   // the ONLY barrier per iteration

        // ---- replicated projection (vectorized reads, rsqrt) ----
        float4 pv0 = *(const float4*)prods;
        float4 pv1 = *(const float4*)(prods + 4);
        const float pr = ((pv0.x + pv0.y) + (pv0.z + pv0.w))
                       + ((pv1.x + pv1.y) + (pv1.z + pv1.w));
        const float kin = KAPPA * rsqrtf(fmaxf(pr, 1e-12f));

        float y1v[8], y2v[8];
        {
            const float4 a0 = *(const float4*)(y1s + lane * 8);
            const float4 a1 = *(const float4*)(y1s + lane * 8 + 4);
            const float4 b0v = *(const float4*)(y2s + lane * 8);
            const float4 b1v = *(const float4*)(y2s + lane * 8 + 4);
            y1v[0] = a0.x; y1v[1] = a0.y; y1v[2] = a0.z; y1v[3] = a0.w;
            y1v[4] = a1.x; y1v[5] = a1.y; y1v[6] = a1.z; y1v[7] = a1.w;
            y2v[0] = b0v.x; y2v[1] = b0v.y; y2v[2] = b0v.z; y2v[3] = b0v.w;
            y2v[4] = b1v.x; y2v[5] = b1v.y; y2v[6] = b1v.z; y2v[7] = b1v.w;
        }

        float v[8];
        #pragma unroll
        for (int k = 0; k < 8; k++) {
            const float grad = -mu_r[k] + LAMBD * y1v[k] + kin * y2v[k];
            v[k] = wv[k] - step * grad;
        }

        // Warm-started Newton on f(tau) = sum(relu(v-tau)) - 1.
        // Convexity: every Newton step lands at/below the root, then monotone.
        float tt = tau;
        bool fb = false;
        for (int ni = 0; ni < 8; ni++) {
            float s = 0.f;
            int cnt = 0;
            #pragma unroll
            for (int k = 0; k < 8; k++) {
                const float d = v[k] - tt;
                if (d > 0.f) { s += d; cnt++; }
            }
            cnt = __reduce_add_sync(0xFFFFFFFFu, cnt);
            #pragma unroll
            for (int o = 16; o; o >>= 1)
                s += __shfl_xor_sync(0xFFFFFFFFu, s, o);
            if (cnt == 0) {
                if (fb) break;
                fb = true;
                float S = 0.f;
                #pragma unroll
                for (int k = 0; k < 8; k++) S += v[k];
                #pragma unroll
                for (int o = 16; o; o >>= 1)
                    S += __shfl_xor_sync(0xFFFFFFFFu, S, o);
                tt = (S - 1.0f) * (1.0f / (float)N_SZ);
                continue;
            }
            const float delta = (s - 1.0f) / (float)cnt;
            tt += delta;
            if (fabsf(delta) <= 1e-10f) break;
        }
        tau = tt;

        #pragma unroll
        for (int k = 0; k < 8; k++) {
            wv[k] = fmaxf(v[k] - tau, 0.f);
            const __half h = __float2half_rn(wv[k]);
            asm volatile("st.shared.u16 [%0], %1;"
                         :: "r"(wpriv + (uint32_t)k * 64 + lane_woff),
                            "h"(__half_as_ushort(h)) : "memory");
        }
        __syncwarp();
    }

    // ---- final clamp + renormalize (warp 0 writes) ----
    if (r == 0) {
        float s = 0.f;
        #pragma unroll
        for (int k = 0; k < 8; k++) { wv[k] = fmaxf(wv[k], 0.f); s += wv[k]; }
        #pragma unroll
        for (int o = 16; o; o >>= 1) s += __shfl_xor_sync(0xFFFFFFFFu, s, o);
        const float inv = 1.0f / (s + 1e-12f);
        #pragma unroll
        for (int k = 0; k < 8; k++)
            out[(size_t)b * N_SZ + lane + (k << 5)] = wv[k] * inv;
    }
}

// ---------------------------------------------------------------------------
// Launcher
// ---------------------------------------------------------------------------
extern "C" void kernel_launch(void* const* d_in, const int* in_sizes, int n_in,
                              void* d_out, int out_size) {
    const float* mu = (const float*)d_in[0];
    const float* U  = (const float*)d_in[1];
    const float* A  = (const float*)d_in[2];
    float* out = (float*)d_out;

    cudaFuncSetAttribute(syrk16_kernel, cudaFuncAttributeMaxDynamicSharedMemorySize,
                         SYRK_SMEM);
    cudaFuncSetAttribute(pgd_mma_kernel, cudaFuncAttributeMaxDynamicSharedMemorySize,
                         SM_TOTAL);

    syrk16_kernel<<<2 * B_SZ, 256, SYRK_SMEM>>>(U, A);
    pgd_mma_kernel<<<B_SZ, 256, SM_TOTAL>>>(mu, out);
}

// round 16
// speedup vs baseline: 1.9431x; 1.1810x over previous
#include <cuda_runtime.h>
#include <cuda_fp16.h>
#include <math.h>
#include <stdint.h>

// Problem constants
#define B_SZ    512
#define N_SZ    256
#define N_ITERS 400
#define LAMBD   1.0f
#define KAPPA   0.1f

// 32x32 tiles over the 8x8 tile-grid upper triangle: 36 tiles per matrix.
#define NTILES 36
__constant__ int c_TA[NTILES] = {0,0,0,0,0,0,0,0, 1,1,1,1,1,1,1, 2,2,2,2,2,2,
                                 3,3,3,3,3, 4,4,4,4, 5,5,5, 6,6, 7};
__constant__ int c_TB[NTILES] = {0,1,2,3,4,5,6,7, 1,2,3,4,5,6,7, 2,3,4,5,6,7,
                                 3,4,5,6,7, 4,5,6,7, 5,6,7, 6,7, 7};

__device__ __forceinline__ int tri_idx(int a, int b) {  // a <= b
    return a * 8 - (a * (a - 1)) / 2 + (b - a);
}

// fp16 G tile store: 32 rows x 40 halves (80B stride)
#define TILE_STRIDE_B 80
#define TILE_BYTES    (32 * TILE_STRIDE_B)      // 2560
#define MAT_BYTES     (NTILES * TILE_BYTES)     // 92160
#define BATCH_BYTES   (2 * MAT_BYTES)           // 184320

__device__ unsigned char g_G16[(size_t)B_SZ * BATCH_BYTES];  // ~94 MB
__device__ float g_fro[2 * B_SZ];

// ---------------------------------------------------------------------------
// PTX helpers (base PTX only; no 'a'-gated instructions)
// ---------------------------------------------------------------------------
__device__ __forceinline__ uint32_t smem_u32(const void* p) {
    uint32_t a;
    asm("{ .reg .u64 t; cvta.to.shared.u64 t, %1; cvt.u32.u64 %0, t; }"
        : "=r"(a) : "l"(p));
    return a;
}
__device__ __forceinline__ void ldsm4(uint32_t& a0, uint32_t& a1, uint32_t& a2,
                                      uint32_t& a3, uint32_t addr) {
    asm volatile("ldmatrix.sync.aligned.m8n8.x4.shared.b16 {%0,%1,%2,%3}, [%4];"
                 : "=r"(a0), "=r"(a1), "=r"(a2), "=r"(a3) : "r"(addr));
}
__device__ __forceinline__ void ldsm4t(uint32_t& a0, uint32_t& a1, uint32_t& a2,
                                       uint32_t& a3, uint32_t addr) {
    asm volatile("ldmatrix.sync.aligned.m8n8.x4.trans.shared.b16 {%0,%1,%2,%3}, [%4];"
                 : "=r"(a0), "=r"(a1), "=r"(a2), "=r"(a3) : "r"(addr));
}
__device__ __forceinline__ void ldsm2t(uint32_t& r0, uint32_t& r1, uint32_t addr) {
    asm volatile("ldmatrix.sync.aligned.m8n8.x2.trans.shared.b16 {%0,%1}, [%2];"
                 : "=r"(r0), "=r"(r1) : "r"(addr));
}
__device__ __forceinline__ void mma16816(float* c, uint32_t a0, uint32_t a1,
                                         uint32_t a2, uint32_t a3,
                                         uint32_t b0, uint32_t b1) {
    asm volatile(
        "mma.sync.aligned.m16n8k16.row.col.f32.f16.f16.f32 "
        "{%0,%1,%2,%3}, {%4,%5,%6,%7}, {%8,%9}, {%0,%1,%2,%3};"
        : "+f"(c[0]), "+f"(c[1]), "+f"(c[2]), "+f"(c[3])
        : "r"(a0), "r"(a1), "r"(a2), "r"(a3), "r"(b0), "r"(b1));
}
__device__ __forceinline__ void mma16816h(uint32_t* c, uint32_t a0, uint32_t a1,
                                          uint32_t a2, uint32_t a3,
                                          uint32_t b0, uint32_t b1) {
    asm volatile(
        "mma.sync.aligned.m16n8k16.row.col.f16.f16.f16.f16 "
        "{%0,%1}, {%2,%3,%4,%5}, {%6,%7}, {%0,%1};"
        : "+r"(c[0]), "+r"(c[1])
        : "r"(a0), "r"(a1), "r"(a2), "r"(a3), "r"(b0), "r"(b1));
}

// ---------------------------------------------------------------------------
// Kernel 1: batched SYRK via HMMA with split-fp16 inputs (unchanged from R8).
// ---------------------------------------------------------------------------
#define XS_STRIDE 528
#define XS_LBASE  (128 * XS_STRIDE)
#define XS_SCR    (2 * 128 * XS_STRIDE)
#define SYRK_SMEM (XS_SCR + 64)

__global__ __launch_bounds__(256, 1) void syrk16_kernel(const float* __restrict__ U,
                                                        const float* __restrict__ A) {
    extern __shared__ unsigned char sm[];
    const uint32_t smb = smem_u32(sm);
    const int mat = blockIdx.x >> 9;
    const int b = blockIdx.x & (B_SZ - 1);
    const float* __restrict__ X = (mat ? A : U) + (size_t)b * (N_SZ * N_SZ);
    const int t = threadIdx.x;
    const int lane = t & 31;
    const int w = t >> 5;

    const uint32_t lane_tr = (uint32_t)((lane & 7) + ((lane & 16) >> 1)) * XS_STRIDE
                           + (uint32_t)(lane & 8) * 2;
    const uint32_t laneB = (uint32_t)(lane & 15) * XS_STRIDE;

    float fro = 0.f;
    float acc[5][2][4][4];
    #pragma unroll
    for (int q = 0; q < 5; q++)
        #pragma unroll
        for (int mh = 0; mh < 2; mh++)
            #pragma unroll
            for (int nq = 0; nq < 4; nq++)
                #pragma unroll
                for (int e = 0; e < 4; e++) acc[q][mh][nq][e] = 0.f;

    #pragma unroll 1
    for (int ch = 0; ch < 2; ch++) {
        if (ch) __syncthreads();
        #pragma unroll 4
        for (int idx = t; idx < 128 * 128; idx += 256) {
            const int ir = idx >> 7;
            const int jp = idx & 127;
            const float2 f = *(const float2*)(X + (size_t)(128 * ch + ir) * N_SZ + 2 * jp);
            fro = fmaf(f.x, f.x, fro);
            fro = fmaf(f.y, f.y, fro);
            const __half hx = __float2half_rn(f.x);
            const __half hy = __float2half_rn(f.y);
            const __half lx = __float2half_rn(f.x - __half2float(hx));
            const __half ly = __float2half_rn(f.y - __half2float(hy));
            *(__half2*)(sm + ir * XS_STRIDE + jp * 4) = __halves2half2(hx, hy);
            *(__half2*)(sm + XS_LBASE + ir * XS_STRIDE + jp * 4) = __halves2half2(lx, ly);
        }
        __syncthreads();

        #pragma unroll
        for (int q = 0; q < 5; q++) {
            const int tix = w + 8 * q;
            if (tix < NTILES) {
                const int a0 = c_TA[tix], b0 = c_TB[tix];
                const uint32_t acol = smb + (uint32_t)(a0 * 32) * 2 + lane_tr;
                const uint32_t bcol = smb + (uint32_t)(b0 * 32) * 2 + laneB;
                #pragma unroll
                for (int kc = 0; kc < 8; kc++) {
                    const uint32_t ro = (uint32_t)(kc * 16) * XS_STRIDE;
                    uint32_t AH[2][4], AL[2][4];
                    #pragma unroll
                    for (int mh = 0; mh < 2; mh++) {
                        const uint32_t ao = acol + ro + (uint32_t)(mh * 16) * 2;
                        ldsm4t(AH[mh][0], AH[mh][1], AH[mh][2], AH[mh][3], ao);
                        ldsm4t(AL[mh][0], AL[mh][1], AL[mh][2], AL[mh][3],
                               ao + XS_LBASE);
                    }
                    #pragma unroll
                    for (int nq = 0; nq < 4; nq++) {
                        const uint32_t bo = bcol + ro + (uint32_t)(nq * 8) * 2;
                        uint32_t bh0, bh1, bl0, bl1;
                        ldsm2t(bh0, bh1, bo);
                        ldsm2t(bl0, bl1, bo + XS_LBASE);
                        #pragma unroll
                        for (int mh = 0; mh < 2; mh++) {
                            float* c = acc[q][mh][nq];
                            mma16816(c, AH[mh][0], AH[mh][1], AH[mh][2], AH[mh][3],
                                     bh0, bh1);
                            mma16816(c, AH[mh][0], AH[mh][1], AH[mh][2], AH[mh][3],
                                     bl0, bl1);
                            mma16816(c, AL[mh][0], AL[mh][1], AL[mh][2], AL[mh][3],
                                     bh0, bh1);
                        }
                    }
                }
            }
        }
    }

    unsigned char* gb = g_G16 + (size_t)b * BATCH_BYTES + (size_t)mat * MAT_BYTES;
    #pragma unroll
    for (int q = 0; q < 5; q++) {
        const int tix = w + 8 * q;
        if (tix < NTILES) {
            #pragma unroll
            for (int mh = 0; mh < 2; mh++)
                #pragma unroll
                for (int nq = 0; nq < 4; nq++) {
                    const float* c = acc[q][mh][nq];
                    const uint32_t o = (uint32_t)tix * TILE_BYTES
                        + (uint32_t)(mh * 16 + (lane >> 2)) * TILE_STRIDE_B
                        + (uint32_t)(nq * 4 + (lane & 3)) * 4;
                    *(__half2*)(gb + o) =
                        __halves2half2(__float2half_rn(c[0]), __float2half_rn(c[1]));
                    *(__half2*)(gb + o + 8 * TILE_STRIDE_B) =
                        __halves2half2(__float2half_rn(c[2]), __float2half_rn(c[3]));
                }
        }
    }

    #pragma unroll
    for (int o = 16; o; o >>= 1) fro += __shfl_xor_sync(0xFFFFFFFFu, fro, o);
    float* scr = (float*)(sm + XS_SCR);
    if (lane == 0) scr[w] = fro;
    __syncthreads();
    if (t == 0) {
        float s = 0.f;
        #pragma unroll
        for (int qq = 0; qq < 8; qq++) s += scr[qq];
        g_fro[mat * B_SZ + b] = s;
    }
}

// ---------------------------------------------------------------------------
// Kernel 2: 400-iteration PGD (R15 champion + critical-path cuts):
//   - prod (w.G2w) computed POST-barrier from the y2 vector loads the
//     projection needs anyway (pre-barrier path = just the y stores)
//   - y vector loads hoisted above the prod reduce (LDS latency overlap)
//   - Newton: 2 unconditional warm steps, then rare fallback loop
// ---------------------------------------------------------------------------
#define SM_WPRIV 0                               // 8 warps x 512 B packed w
#define SM_Y1    4096                            // [2][256] f32 transposed
#define SM_Y2    6144
#define SM_TILES 10240
#define SM_TOTAL (SM_TILES + BATCH_BYTES)        // 194560

__global__ __launch_bounds__(256, 1) void pgd_mma_kernel(const float* __restrict__ mu,
                                                         float* __restrict__ out) {
    extern __shared__ unsigned char sm[];
    const uint32_t smb = smem_u32(sm);
    const int b = blockIdx.x;
    const int t = threadIdx.x;
    const int lane = t & 31;
    const int r = t >> 5;                   // warp id == output band

    // ---- init: raw copy of both fp16 triangles ----
    {
        const uint4* src = (const uint4*)(g_G16 + (size_t)b * BATCH_BYTES);
        uint4* dst = (uint4*)(sm + SM_TILES);
        #pragma unroll 4
        for (int i = t; i < BATCH_BYTES / 16; i += 256) dst[i] = src[i];
    }

    const uint32_t t1base = smb + SM_TILES;
    const uint32_t t2base = smb + SM_TILES + MAT_BYTES;
    const uint32_t wpriv = smb + SM_WPRIV + (uint32_t)r * 512;

    const uint32_t lane_nt = (uint32_t)((lane & 7) + (lane & 8)) * TILE_STRIDE_B
                           + (uint32_t)((lane & 16) >> 1) * 2;
    const uint32_t lane_tr = (uint32_t)((lane & 7) + ((lane & 16) >> 1)) * TILE_STRIDE_B
                           + (uint32_t)(lane & 8) * 2;

    // packed-w writer offset (R12 layout, validated)
    const int pw = lane & 15;
    const uint32_t lane_woff = (uint32_t)(((lane >> 4) & 1) * 4 + ((pw >> 1) & 3)) * 8
                             + (uint32_t)((((pw >> 3) << 1) | (pw & 1)) * 2);

    const float step = 1.0f / (LAMBD * g_fro[b] + KAPPA * sqrtf(g_fro[B_SZ + b]) + 1.0f);

    __syncthreads();

    // ---- preload k-bands 0..4 into registers (160 frag regs) ----
    uint32_t fr[2][5][2][2][4];
    #pragma unroll
    for (int m = 0; m < 2; m++) {
        const uint32_t tb = m ? t2base : t1base;
        #pragma unroll
        for (int bb = 0; bb < 5; bb++) {
            const bool trp = (bb < r);
            const int aa = trp ? bb : r;
            const int bn = trp ? r : bb;
            const uint32_t tile = tb + (uint32_t)tri_idx(aa, bn) * TILE_BYTES;
            #pragma unroll
            for (int ks = 0; ks < 2; ks++) {
                if (trp) {
                    const uint32_t o = (uint32_t)ks * (16 * TILE_STRIDE_B) + lane_tr;
                    ldsm4t(fr[m][bb][ks][0][0], fr[m][bb][ks][0][1],
                           fr[m][bb][ks][0][2], fr[m][bb][ks][0][3], tile + o);
                    ldsm4t(fr[m][bb][ks][1][0], fr[m][bb][ks][1][1],
                           fr[m][bb][ks][1][2], fr[m][bb][ks][1][3], tile + o + 32);
                } else {
                    const uint32_t o = (uint32_t)ks * 32 + lane_nt;
                    ldsm4(fr[m][bb][ks][0][0], fr[m][bb][ks][0][1],
                          fr[m][bb][ks][0][2], fr[m][bb][ks][0][3], tile + o);
                    ldsm4(fr[m][bb][ks][1][0], fr[m][bb][ks][1][1],
                          fr[m][bb][ks][1][2], fr[m][bb][ks][1][3],
                          tile + o + 16 * TILE_STRIDE_B);
                }
            }
        }
    }

    // ---- replicated solver state (identical in every warp) ----
    float wv[8], mu_r[8];
    float tau = 0.0f;
    #pragma unroll
    for (int k = 0; k < 8; k++) {
        wv[k] = 1.0f / (float)N_SZ;
        mu_r[k] = mu[(size_t)b * N_SZ + lane + (k << 5)];
        const __half h = __float2half_rn(wv[k]);
        asm volatile("st.shared.u16 [%0], %1;"
                     :: "r"(wpriv + (uint32_t)k * 64 + lane_woff),
                        "h"(__half_as_ushort(h)) : "memory");
    }
    __syncwarp();
    __syncthreads();

    #pragma unroll 1
    for (int it = 0; it < N_ITERS; it++) {
        const uint32_t buf = (uint32_t)(it & 1);
        float* const y1s = (float*)(sm + SM_Y1 + buf * 1024);
        float* const y2s = (float*)(sm + SM_Y2 + buf * 1024);

        float c1A[4] = {0.f,0.f,0.f,0.f}, c1B[4] = {0.f,0.f,0.f,0.f};
        uint32_t h2A[2] = {0u, 0u}, h2B[2] = {0u, 0u};   // G2 fp16 accumulators

        // ---- STREAMED k-bands 5..7 FIRST (LDSM latency hidden) ----
        #pragma unroll
        for (int bb = 5; bb < 8; bb++) {
            const bool trp = (bb < r);
            const int aa = trp ? bb : r;
            const int bn = trp ? r : bb;
            const uint32_t toff = (uint32_t)tri_idx(aa, bn) * TILE_BYTES;
            const uint32_t tile1 = t1base + toff;
            const uint32_t tile2 = t2base + toff;
            #pragma unroll
            for (int ks = 0; ks < 2; ks++) {
                uint32_t b0, b1;
                const uint32_t waddr = wpriv + (uint32_t)((bb * 8 + ks * 4) * 8)
                                     + (uint32_t)(lane & 3) * 8;
                asm volatile("ld.shared.v2.b32 {%0,%1}, [%2];"
                             : "=r"(b0), "=r"(b1) : "r"(waddr));

                uint32_t sA[4][4];
                if (trp) {
                    const uint32_t o = (uint32_t)ks * (16 * TILE_STRIDE_B) + lane_tr;
                    ldsm4t(sA[0][0], sA[0][1], sA[0][2], sA[0][3], tile1 + o);
                    ldsm4t(sA[1][0], sA[1][1], sA[1][2], sA[1][3], tile1 + o + 32);
                    ldsm4t(sA[2][0], sA[2][1], sA[2][2], sA[2][3], tile2 + o);
                    ldsm4t(sA[3][0], sA[3][1], sA[3][2], sA[3][3], tile2 + o + 32);
                } else {
                    const uint32_t o = (uint32_t)ks * 32 + lane_nt;
                    ldsm4(sA[0][0], sA[0][1], sA[0][2], sA[0][3], tile1 + o);
                    ldsm4(sA[1][0], sA[1][1], sA[1][2], sA[1][3],
                          tile1 + o + 16 * TILE_STRIDE_B);
                    ldsm4(sA[2][0], sA[2][1], sA[2][2], sA[2][3], tile2 + o);
                    ldsm4(sA[3][0], sA[3][1], sA[3][2], sA[3][3],
                          tile2 + o + 16 * TILE_STRIDE_B);
                }
                mma16816(c1A, sA[0][0], sA[0][1], sA[0][2], sA[0][3], b0, b1);
                mma16816(c1B, sA[1][0], sA[1][1], sA[1][2], sA[1][3], b0, b1);
                mma16816h(h2A, sA[2][0], sA[2][1], sA[2][2], sA[2][3], b0, b1);
                mma16816h(h2B, sA[3][0], sA[3][1], sA[3][2], sA[3][3], b0, b1);
            }
        }

        // ---- register-resident k-bands 0..4 ----
        #pragma unroll
        for (int bb = 0; bb < 5; bb++) {
            #pragma unroll
            for (int ks = 0; ks < 2; ks++) {
                uint32_t b0, b1;
                const uint32_t waddr = wpriv + (uint32_t)((bb * 8 + ks * 4) * 8)
                                     + (uint32_t)(lane & 3) * 8;
                asm volatile("ld.shared.v2.b32 {%0,%1}, [%2];"
                             : "=r"(b0), "=r"(b1) : "r"(waddr));

                mma16816(c1A, fr[0][bb][ks][0][0], fr[0][bb][ks][0][1],
                              fr[0][bb][ks][0][2], fr[0][bb][ks][0][3], b0, b1);
                mma16816(c1B, fr[0][bb][ks][1][0], fr[0][bb][ks][1][1],
                              fr[0][bb][ks][1][2], fr[0][bb][ks][1][3], b0, b1);
                mma16816h(h2A, fr[1][bb][ks][0][0], fr[1][bb][ks][0][1],
                               fr[1][bb][ks][0][2], fr[1][bb][ks][0][3], b0, b1);
                mma16816h(h2B, fr[1][bb][ks][1][0], fr[1][bb][ks][1][1],
                               fr[1][bb][ks][1][2], fr[1][bb][ks][1][3], b0, b1);
            }
        }

        // ---- extract G2 results (col 0 = low half of each f16x2 pair) ----
        const float c2A0 = __low2float(*(const __half2*)&h2A[0]);
        const float c2A2 = __low2float(*(const __half2*)&h2A[1]);
        const float c2B0 = __low2float(*(const __half2*)&h2B[0]);
        const float c2B2 = __low2float(*(const __half2*)&h2B[1]);

        // ---- pre-barrier: ONLY the y stores (prod moved post-barrier) ----
        const int g = lane >> 2;
        if ((lane & 3) == 0) {
            y1s[g * 8 + r]        = c1A[0];
            y1s[(g + 8) * 8 + r]  = c1A[2];
            y1s[(g + 16) * 8 + r] = c1B[0];
            y1s[(g + 24) * 8 + r] = c1B[2];
            y2s[g * 8 + r]        = c2A0;
            y2s[(g + 8) * 8 + r]  = c2A2;
            y2s[(g + 16) * 8 + r] = c2B0;
            y2s[(g + 24) * 8 + r] = c2B2;
        }
        __syncthreads();   // the ONLY barrier per iteration

        // ---- replicated projection: y loads first (latency overlap) ----
        float y1v[8], y2v[8];
        {
            const float4 a0 = *(const float4*)(y1s + lane * 8);
            const float4 a1 = *(const float4*)(y1s + lane * 8 + 4);
            const float4 b0v = *(const float4*)(y2s + lane * 8);
            const float4 b1v = *(const float4*)(y2s + lane * 8 + 4);
            y1v[0] = a0.x; y1v[1] = a0.y; y1v[2] = a0.z; y1v[3] = a0.w;
            y1v[4] = a1.x; y1v[5] = a1.y; y1v[6] = a1.z; y1v[7] = a1.w;
            y2v[0] = b0v.x; y2v[1] = b0v.y; y2v[2] = b0v.z; y2v[3] = b0v.w;
            y2v[4] = b1v.x; y2v[5] = b1v.y; y2v[6] = b1v.z; y2v[7] = b1v.w;
        }

        // prod = w.(G2 w): per-thread partial over own coords, butterfly reduce
        float pr = 0.f;
        #pragma unroll
        for (int k = 0; k < 8; k++) pr = fmaf(wv[k], y2v[k], pr);
        #pragma unroll
        for (int o = 16; o; o >>= 1) pr += __shfl_xor_sync(0xFFFFFFFFu, pr, o);
        const float kin = KAPPA * rsqrtf(fmaxf(pr, 1e-12f));

        float v[8];
        #pragma unroll
        for (int k = 0; k < 8; k++) {
            const float grad = -mu_r[k] + LAMBD * y1v[k] + kin * y2v[k];
            v[k] = wv[k] - step * grad;
        }

        // Warm-started Newton on f(tau)=sum(relu(v-tau))-1: two unconditional
        // steps (convex pw-linear: tangent roots never overshoot), then a rare
        // fallback loop for active-set edge cases.
        float tt = tau;
        float s0 = 0.f; int c0 = 0;
        #pragma unroll
        for (int k = 0; k < 8; k++) {
            const float d = v[k] - tt;
            if (d > 0.f) { s0 += d; c0++; }
        }
        c0 = __reduce_add_sync(0xFFFFFFFFu, c0);
        #pragma unroll
        for (int o = 16; o; o >>= 1) s0 += __shfl_xor_sync(0xFFFFFFFFu, s0, o);
        if (c0 > 0) tt += (s0 - 1.0f) / (float)c0;

        float s1 = 0.f; int c1 = 0;
        #pragma unroll
        for (int k = 0; k < 8; k++) {
            const float d = v[k] - tt;
            if (d > 0.f) { s1 += d; c1++; }
        }
        c1 = __reduce_add_sync(0xFFFFFFFFu, c1);
        #pragma unroll
        for (int o = 16; o; o >>= 1) s1 += __shfl_xor_sync(0xFFFFFFFFu, s1, o);

        if (c0 == 0 || c1 == 0 || fabsf(s1 - 1.0f) > 1e-9f * (float)c1) {
            // fallback: restart from the global lower bound, iterate to root
            float S = 0.f;
            #pragma unroll
            for (int k = 0; k < 8; k++) S += v[k];
            #pragma unroll
            for (int o = 16; o; o >>= 1) S += __shfl_xor_sync(0xFFFFFFFFu, S, o);
            tt = (S - 1.0f) * (1.0f / (float)N_SZ);
            for (int ni = 0; ni < 10; ni++) {
                float s = 0.f; int cnt = 0;
                #pragma unroll
                for (int k = 0; k < 8; k++) {
                    const float d = v[k] - tt;
                    if (d > 0.f) { s += d; cnt++; }
                }
                cnt = __reduce_add_sync(0xFFFFFFFFu, cnt);
                #pragma unroll
                for (int o = 16; o; o >>= 1)
                    s += __shfl_xor_sync(0xFFFFFFFFu, s, o);
                if (cnt == 0) break;
                const float delta = (s - 1.0f) / (float)cnt;
                tt += delta;
                if (fabsf(delta) <= 1e-10f) break;
            }
        }
        tau = tt;

        #pragma unroll
        for (int k = 0; k < 8; k++) {
            wv[k] = fmaxf(v[k] - tau, 0.f);
            const __half h = __float2half_rn(wv[k]);
            asm volatile("st.shared.u16 [%0], %1;"
                         :: "r"(wpriv + (uint32_t)k * 64 + lane_woff),
                            "h"(__half_as_ushort(h)) : "memory");
        }
        __syncwarp();
    }

    // ---- final clamp + renormalize (warp 0 writes) ----
    if (r == 0) {
        float s = 0.f;
        #pragma unroll
        for (int k = 0; k < 8; k++) { wv[k] = fmaxf(wv[k], 0.f); s += wv[k]; }
        #pragma unroll
        for (int o = 16; o; o >>= 1) s += __shfl_xor_sync(0xFFFFFFFFu, s, o);
        const float inv = 1.0f / (s + 1e-12f);
        #pragma unroll
        for (int k = 0; k < 8; k++)
            out[(size_t)b * N_SZ + lane + (k << 5)] = wv[k] * inv;
    }
}

// ---------------------------------------------------------------------------
// Launcher
// ---------------------------------------------------------------------------
extern "C" void kernel_launch(void* const* d_in, const int* in_sizes, int n_in,
                              void* d_out, int out_size) {
    const float* mu = (const float*)d_in[0];
    const float* U  = (const float*)d_in[1];
    const float* A  = (const float*)d_in[2];
    float* out = (float*)d_out;

    cudaFuncSetAttribute(syrk16_kernel, cudaFuncAttributeMaxDynamicSharedMemorySize,
                         SYRK_SMEM);
    cudaFuncSetAttribute(pgd_mma_kernel, cudaFuncAttributeMaxDynamicSharedMemorySize,
                         SM_TOTAL);

    syrk16_kernel<<<2 * B_SZ, 256, SYRK_SMEM>>>(U, A);
    pgd_mma_kernel<<<B_SZ, 256, SM_TOTAL>>>(mu, out);
}

// round 17
// speedup vs baseline: 2.0409x; 1.0504x over previous
#include <cuda_runtime.h>
#include <cuda_fp16.h>
#include <math.h>
#include <stdint.h>

// Problem constants
#define B_SZ    512
#define N_SZ    256
#define N_ITERS 400
#define LAMBD   1.0f
#define KAPPA   0.1f

// 32x32 tiles over the 8x8 tile-grid upper triangle: 36 tiles per matrix.
#define NTILES 36
__constant__ int c_TA[NTILES] = {0,0,0,0,0,0,0,0, 1,1,1,1,1,1,1, 2,2,2,2,2,2,
                                 3,3,3,3,3, 4,4,4,4, 5,5,5, 6,6, 7};
__constant__ int c_TB[NTILES] = {0,1,2,3,4,5,6,7, 1,2,3,4,5,6,7, 2,3,4,5,6,7,
                                 3,4,5,6,7, 4,5,6,7, 5,6,7, 6,7, 7};

__device__ __forceinline__ int tri_idx(int a, int b) {  // a <= b
    return a * 8 - (a * (a - 1)) / 2 + (b - a);
}

// fp16 G tile store: 32 rows x 40 halves (80B stride)
#define TILE_STRIDE_B 80
#define TILE_BYTES    (32 * TILE_STRIDE_B)      // 2560
#define MAT_BYTES     (NTILES * TILE_BYTES)     // 92160
#define BATCH_BYTES   (2 * MAT_BYTES)           // 184320

__device__ unsigned char g_G16[(size_t)B_SZ * BATCH_BYTES];  // ~94 MB
__device__ float g_fro[2 * B_SZ];

// Fixed-point scale for Newton sum reduction (s in [0, ~9] per thread)
#define FXS 4194304.0f        // 2^22
#define FXS_INV (1.0f / 4194304.0f)

// ---------------------------------------------------------------------------
// PTX helpers (base PTX only; no 'a'-gated instructions)
// ---------------------------------------------------------------------------
__device__ __forceinline__ uint32_t smem_u32(const void* p) {
    uint32_t a;
    asm("{ .reg .u64 t; cvta.to.shared.u64 t, %1; cvt.u32.u64 %0, t; }"
        : "=r"(a) : "l"(p));
    return a;
}
__device__ __forceinline__ void ldsm4(uint32_t& a0, uint32_t& a1, uint32_t& a2,
                                      uint32_t& a3, uint32_t addr) {
    asm volatile("ldmatrix.sync.aligned.m8n8.x4.shared.b16 {%0,%1,%2,%3}, [%4];"
                 : "=r"(a0), "=r"(a1), "=r"(a2), "=r"(a3) : "r"(addr));
}
__device__ __forceinline__ void ldsm4t(uint32_t& a0, uint32_t& a1, uint32_t& a2,
                                       uint32_t& a3, uint32_t addr) {
    asm volatile("ldmatrix.sync.aligned.m8n8.x4.trans.shared.b16 {%0,%1,%2,%3}, [%4];"
                 : "=r"(a0), "=r"(a1), "=r"(a2), "=r"(a3) : "r"(addr));
}
__device__ __forceinline__ void ldsm2t(uint32_t& r0, uint32_t& r1, uint32_t addr) {
    asm volatile("ldmatrix.sync.aligned.m8n8.x2.trans.shared.b16 {%0,%1}, [%2];"
                 : "=r"(r0), "=r"(r1) : "r"(addr));
}
__device__ __forceinline__ void mma16816(float* c, uint32_t a0, uint32_t a1,
                                         uint32_t a2, uint32_t a3,
                                         uint32_t b0, uint32_t b1) {
    asm volatile(
        "mma.sync.aligned.m16n8k16.row.col.f32.f16.f16.f32 "
        "{%0,%1,%2,%3}, {%4,%5,%6,%7}, {%8,%9}, {%0,%1,%2,%3};"
        : "+f"(c[0]), "+f"(c[1]), "+f"(c[2]), "+f"(c[3])
        : "r"(a0), "r"(a1), "r"(a2), "r"(a3), "r"(b0), "r"(b1));
}
__device__ __forceinline__ void mma16816h(uint32_t* c, uint32_t a0, uint32_t a1,
                                          uint32_t a2, uint32_t a3,
                                          uint32_t b0, uint32_t b1) {
    asm volatile(
        "mma.sync.aligned.m16n8k16.row.col.f16.f16.f16.f16 "
        "{%0,%1}, {%2,%3,%4,%5}, {%6,%7}, {%0,%1};"
        : "+r"(c[0]), "+r"(c[1])
        : "r"(a0), "r"(a1), "r"(a2), "r"(a3), "r"(b0), "r"(b1));
}

// ---------------------------------------------------------------------------
// Kernel 1: batched SYRK via HMMA with split-fp16 inputs (unchanged from R8).
// ---------------------------------------------------------------------------
#define XS_STRIDE 528
#define XS_LBASE  (128 * XS_STRIDE)
#define XS_SCR    (2 * 128 * XS_STRIDE)
#define SYRK_SMEM (XS_SCR + 64)

__global__ __launch_bounds__(256, 1) void syrk16_kernel(const float* __restrict__ U,
                                                        const float* __restrict__ A) {
    extern __shared__ unsigned char sm[];
    const uint32_t smb = smem_u32(sm);
    const int mat = blockIdx.x >> 9;
    const int b = blockIdx.x & (B_SZ - 1);
    const float* __restrict__ X = (mat ? A : U) + (size_t)b * (N_SZ * N_SZ);
    const int t = threadIdx.x;
    const int lane = t & 31;
    const int w = t >> 5;

    const uint32_t lane_tr = (uint32_t)((lane & 7) + ((lane & 16) >> 1)) * XS_STRIDE
                           + (uint32_t)(lane & 8) * 2;
    const uint32_t laneB = (uint32_t)(lane & 15) * XS_STRIDE;

    float fro = 0.f;
    float acc[5][2][4][4];
    #pragma unroll
    for (int q = 0; q < 5; q++)
        #pragma unroll
        for (int mh = 0; mh < 2; mh++)
            #pragma unroll
            for (int nq = 0; nq < 4; nq++)
                #pragma unroll
                for (int e = 0; e < 4; e++) acc[q][mh][nq][e] = 0.f;

    #pragma unroll 1
    for (int ch = 0; ch < 2; ch++) {
        if (ch) __syncthreads();
        #pragma unroll 4
        for (int idx = t; idx < 128 * 128; idx += 256) {
            const int ir = idx >> 7;
            const int jp = idx & 127;
            const float2 f = *(const float2*)(X + (size_t)(128 * ch + ir) * N_SZ + 2 * jp);
            fro = fmaf(f.x, f.x, fro);
            fro = fmaf(f.y, f.y, fro);
            const __half hx = __float2half_rn(f.x);
            const __half hy = __float2half_rn(f.y);
            const __half lx = __float2half_rn(f.x - __half2float(hx));
            const __half ly = __float2half_rn(f.y - __half2float(hy));
            *(__half2*)(sm + ir * XS_STRIDE + jp * 4) = __halves2half2(hx, hy);
            *(__half2*)(sm + XS_LBASE + ir * XS_STRIDE + jp * 4) = __halves2half2(lx, ly);
        }
        __syncthreads();

        #pragma unroll
        for (int q = 0; q < 5; q++) {
            const int tix = w + 8 * q;
            if (tix < NTILES) {
                const int a0 = c_TA[tix], b0 = c_TB[tix];
                const uint32_t acol = smb + (uint32_t)(a0 * 32) * 2 + lane_tr;
                const uint32_t bcol = smb + (uint32_t)(b0 * 32) * 2 + laneB;
                #pragma unroll
                for (int kc = 0; kc < 8; kc++) {
                    const uint32_t ro = (uint32_t)(kc * 16) * XS_STRIDE;
                    uint32_t AH[2][4], AL[2][4];
                    #pragma unroll
                    for (int mh = 0; mh < 2; mh++) {
                        const uint32_t ao = acol + ro + (uint32_t)(mh * 16) * 2;
                        ldsm4t(AH[mh][0], AH[mh][1], AH[mh][2], AH[mh][3], ao);
                        ldsm4t(AL[mh][0], AL[mh][1], AL[mh][2], AL[mh][3],
                               ao + XS_LBASE);
                    }
                    #pragma unroll
                    for (int nq = 0; nq < 4; nq++) {
                        const uint32_t bo = bcol + ro + (uint32_t)(nq * 8) * 2;
                        uint32_t bh0, bh1, bl0, bl1;
                        ldsm2t(bh0, bh1, bo);
                        ldsm2t(bl0, bl1, bo + XS_LBASE);
                        #pragma unroll
                        for (int mh = 0; mh < 2; mh++) {
                            float* c = acc[q][mh][nq];
                            mma16816(c, AH[mh][0], AH[mh][1], AH[mh][2], AH[mh][3],
                                     bh0, bh1);
                            mma16816(c, AH[mh][0], AH[mh][1], AH[mh][2], AH[mh][3],
                                     bl0, bl1);
                            mma16816(c, AL[mh][0], AL[mh][1], AL[mh][2], AL[mh][3],
                                     bh0, bh1);
                        }
                    }
                }
            }
        }
    }

    unsigned char* gb = g_G16 + (size_t)b * BATCH_BYTES + (size_t)mat * MAT_BYTES;
    #pragma unroll
    for (int q = 0; q < 5; q++) {
        const int tix = w + 8 * q;
        if (tix < NTILES) {
            #pragma unroll
            for (int mh = 0; mh < 2; mh++)
                #pragma unroll
                for (int nq = 0; nq < 4; nq++) {
                    const float* c = acc[q][mh][nq];
                    const uint32_t o = (uint32_t)tix * TILE_BYTES
                        + (uint32_t)(mh * 16 + (lane >> 2)) * TILE_STRIDE_B
                        + (uint32_t)(nq * 4 + (lane & 3)) * 4;
                    *(__half2*)(gb + o) =
                        __halves2half2(__float2half_rn(c[0]), __float2half_rn(c[1]));
                    *(__half2*)(gb + o + 8 * TILE_STRIDE_B) =
                        __halves2half2(__float2half_rn(c[2]), __float2half_rn(c[3]));
                }
        }
    }

    #pragma unroll
    for (int o = 16; o; o >>= 1) fro += __shfl_xor_sync(0xFFFFFFFFu, fro, o);
    float* scr = (float*)(sm + XS_SCR);
    if (lane == 0) scr[w] = fro;
    __syncthreads();
    if (t == 0) {
        float s = 0.f;
        #pragma unroll
        for (int qq = 0; qq < 8; qq++) s += scr[qq];
        g_fro[mat * B_SZ + b] = s;
    }
}

// ---------------------------------------------------------------------------
// Kernel 2: 400-iteration PGD (R16 champion + serial-chain cuts):
//   - Newton sum reductions via fixed-point __reduce_add_sync (REDUX)
//   - b-frag loads batched per band (both kslices up front)
// ---------------------------------------------------------------------------
#define SM_WPRIV 0                               // 8 warps x 512 B packed w
#define SM_Y1    4096                            // [2][256] f32 transposed
#define SM_Y2    6144
#define SM_TILES 10240
#define SM_TOTAL (SM_TILES + BATCH_BYTES)        // 194560

__global__ __launch_bounds__(256, 1) void pgd_mma_kernel(const float* __restrict__ mu,
                                                         float* __restrict__ out) {
    extern __shared__ unsigned char sm[];
    const uint32_t smb = smem_u32(sm);
    const int b = blockIdx.x;
    const int t = threadIdx.x;
    const int lane = t & 31;
    const int r = t >> 5;                   // warp id == output band

    // ---- init: raw copy of both fp16 triangles ----
    {
        const uint4* src = (const uint4*)(g_G16 + (size_t)b * BATCH_BYTES);
        uint4* dst = (uint4*)(sm + SM_TILES);
        #pragma unroll 4
        for (int i = t; i < BATCH_BYTES / 16; i += 256) dst[i] = src[i];
    }

    const uint32_t t1base = smb + SM_TILES;
    const uint32_t t2base = smb + SM_TILES + MAT_BYTES;
    const uint32_t wpriv = smb + SM_WPRIV + (uint32_t)r * 512;

    const uint32_t lane_nt = (uint32_t)((lane & 7) + (lane & 8)) * TILE_STRIDE_B
                           + (uint32_t)((lane & 16) >> 1) * 2;
    const uint32_t lane_tr = (uint32_t)((lane & 7) + ((lane & 16) >> 1)) * TILE_STRIDE_B
                           + (uint32_t)(lane & 8) * 2;

    // packed-w writer offset (R12 layout, validated)
    const int pw = lane & 15;
    const uint32_t lane_woff = (uint32_t)(((lane >> 4) & 1) * 4 + ((pw >> 1) & 3)) * 8
                             + (uint32_t)((((pw >> 3) << 1) | (pw & 1)) * 2);

    const float step = 1.0f / (LAMBD * g_fro[b] + KAPPA * sqrtf(g_fro[B_SZ + b]) + 1.0f);

    __syncthreads();

    // ---- preload k-bands 0..4 into registers (160 frag regs) ----
    uint32_t fr[2][5][2][2][4];
    #pragma unroll
    for (int m = 0; m < 2; m++) {
        const uint32_t tb = m ? t2base : t1base;
        #pragma unroll
        for (int bb = 0; bb < 5; bb++) {
            const bool trp = (bb < r);
            const int aa = trp ? bb : r;
            const int bn = trp ? r : bb;
            const uint32_t tile = tb + (uint32_t)tri_idx(aa, bn) * TILE_BYTES;
            #pragma unroll
            for (int ks = 0; ks < 2; ks++) {
                if (trp) {
                    const uint32_t o = (uint32_t)ks * (16 * TILE_STRIDE_B) + lane_tr;
                    ldsm4t(fr[m][bb][ks][0][0], fr[m][bb][ks][0][1],
                           fr[m][bb][ks][0][2], fr[m][bb][ks][0][3], tile + o);
                    ldsm4t(fr[m][bb][ks][1][0], fr[m][bb][ks][1][1],
                           fr[m][bb][ks][1][2], fr[m][bb][ks][1][3], tile + o + 32);
                } else {
                    const uint32_t o = (uint32_t)ks * 32 + lane_nt;
                    ldsm4(fr[m][bb][ks][0][0], fr[m][bb][ks][0][1],
                          fr[m][bb][ks][0][2], fr[m][bb][ks][0][3], tile + o);
                    ldsm4(fr[m][bb][ks][1][0], fr[m][bb][ks][1][1],
                          fr[m][bb][ks][1][2], fr[m][bb][ks][1][3],
                          tile + o + 16 * TILE_STRIDE_B);
                }
            }
        }
    }

    // ---- replicated solver state (identical in every warp) ----
    float wv[8], mu_r[8];
    float tau = 0.0f;
    #pragma unroll
    for (int k = 0; k < 8; k++) {
        wv[k] = 1.0f / (float)N_SZ;
        mu_r[k] = mu[(size_t)b * N_SZ + lane + (k << 5)];
        const __half h = __float2half_rn(wv[k]);
        asm volatile("st.shared.u16 [%0], %1;"
                     :: "r"(wpriv + (uint32_t)k * 64 + lane_woff),
                        "h"(__half_as_ushort(h)) : "memory");
    }
    __syncwarp();
    __syncthreads();

    #pragma unroll 1
    for (int it = 0; it < N_ITERS; it++) {
        const uint32_t buf = (uint32_t)(it & 1);
        float* const y1s = (float*)(sm + SM_Y1 + buf * 1024);
        float* const y2s = (float*)(sm + SM_Y2 + buf * 1024);

        float c1A[4] = {0.f,0.f,0.f,0.f}, c1B[4] = {0.f,0.f,0.f,0.f};
        uint32_t h2A[2] = {0u, 0u}, h2B[2] = {0u, 0u};   // G2 fp16 accumulators

        // ---- STREAMED k-bands 5..7 FIRST (LDSM latency hidden) ----
        #pragma unroll
        for (int bb = 5; bb < 8; bb++) {
            const bool trp = (bb < r);
            const int aa = trp ? bb : r;
            const int bn = trp ? r : bb;
            const uint32_t toff = (uint32_t)tri_idx(aa, bn) * TILE_BYTES;
            const uint32_t tile1 = t1base + toff;
            const uint32_t tile2 = t2base + toff;

            // both kslices' b-frags up front: one exposed LDS latency
            uint32_t b0[2], b1[2];
            const uint32_t wbase = wpriv + (uint32_t)(bb * 64)
                                 + (uint32_t)(lane & 3) * 8;
            asm volatile("ld.shared.v2.b32 {%0,%1}, [%2];"
                         : "=r"(b0[0]), "=r"(b1[0]) : "r"(wbase));
            asm volatile("ld.shared.v2.b32 {%0,%1}, [%2];"
                         : "=r"(b0[1]), "=r"(b1[1]) : "r"(wbase + 32));

            #pragma unroll
            for (int ks = 0; ks < 2; ks++) {
                uint32_t sA[4][4];
                if (trp) {
                    const uint32_t o = (uint32_t)ks * (16 * TILE_STRIDE_B) + lane_tr;
                    ldsm4t(sA[0][0], sA[0][1], sA[0][2], sA[0][3], tile1 + o);
                    ldsm4t(sA[1][0], sA[1][1], sA[1][2], sA[1][3], tile1 + o + 32);
                    ldsm4t(sA[2][0], sA[2][1], sA[2][2], sA[2][3], tile2 + o);
                    ldsm4t(sA[3][0], sA[3][1], sA[3][2], sA[3][3], tile2 + o + 32);
                } else {
                    const uint32_t o = (uint32_t)ks * 32 + lane_nt;
                    ldsm4(sA[0][0], sA[0][1], sA[0][2], sA[0][3], tile1 + o);
                    ldsm4(sA[1][0], sA[1][1], sA[1][2], sA[1][3],
                          tile1 + o + 16 * TILE_STRIDE_B);
                    ldsm4(sA[2][0], sA[2][1], sA[2][2], sA[2][3], tile2 + o);
                    ldsm4(sA[3][0], sA[3][1], sA[3][2], sA[3][3],
                          tile2 + o + 16 * TILE_STRIDE_B);
                }
                mma16816(c1A, sA[0][0], sA[0][1], sA[0][2], sA[0][3], b0[ks], b1[ks]);
                mma16816(c1B, sA[1][0], sA[1][1], sA[1][2], sA[1][3], b0[ks], b1[ks]);
                mma16816h(h2A, sA[2][0], sA[2][1], sA[2][2], sA[2][3], b0[ks], b1[ks]);
                mma16816h(h2B, sA[3][0], sA[3][1], sA[3][2], sA[3][3], b0[ks], b1[ks]);
            }
        }

        // ---- register-resident k-bands 0..4 ----
        #pragma unroll
        for (int bb = 0; bb < 5; bb++) {
            uint32_t b0[2], b1[2];
            const uint32_t wbase = wpriv + (uint32_t)(bb * 64)
                                 + (uint32_t)(lane & 3) * 8;
            asm volatile("ld.shared.v2.b32 {%0,%1}, [%2];"
                         : "=r"(b0[0]), "=r"(b1[0]) : "r"(wbase));
            asm volatile("ld.shared.v2.b32 {%0,%1}, [%2];"
                         : "=r"(b0[1]), "=r"(b1[1]) : "r"(wbase + 32));
            #pragma unroll
            for (int ks = 0; ks < 2; ks++) {
                mma16816(c1A, fr[0][bb][ks][0][0], fr[0][bb][ks][0][1],
                              fr[0][bb][ks][0][2], fr[0][bb][ks][0][3], b0[ks], b1[ks]);
                mma16816(c1B, fr[0][bb][ks][1][0], fr[0][bb][ks][1][1],
                              fr[0][bb][ks][1][2], fr[0][bb][ks][1][3], b0[ks], b1[ks]);
                mma16816h(h2A, fr[1][bb][ks][0][0], fr[1][bb][ks][0][1],
                               fr[1][bb][ks][0][2], fr[1][bb][ks][0][3], b0[ks], b1[ks]);
                mma16816h(h2B, fr[1][bb][ks][1][0], fr[1][bb][ks][1][1],
                               fr[1][bb][ks][1][2], fr[1][bb][ks][1][3], b0[ks], b1[ks]);
            }
        }

        // ---- extract G2 results (col 0 = low half of each f16x2 pair) ----
        const float c2A0 = __low2float(*(const __half2*)&h2A[0]);
        const float c2A2 = __low2float(*(const __half2*)&h2A[1]);
        const float c2B0 = __low2float(*(const __half2*)&h2B[0]);
        const float c2B2 = __low2float(*(const __half2*)&h2B[1]);

        // ---- pre-barrier: ONLY the y stores ----
        const int g = lane >> 2;
        if ((lane & 3) == 0) {
            y1s[g * 8 + r]        = c1A[0];
            y1s[(g + 8) * 8 + r]  = c1A[2];
            y1s[(g + 16) * 8 + r] = c1B[0];
            y1s[(g + 24) * 8 + r] = c1B[2];
            y2s[g * 8 + r]        = c2A0;
            y2s[(g + 8) * 8 + r]  = c2A2;
            y2s[(g + 16) * 8 + r] = c2B0;
            y2s[(g + 24) * 8 + r] = c2B2;
        }
        __syncthreads();   // the ONLY barrier per iteration

        // ---- replicated projection: y loads first (latency overlap) ----
        float y1v[8], y2v[8];
        {
            const float4 a0 = *(const float4*)(y1s + lane * 8);
            const float4 a1 = *(const float4*)(y1s + lane * 8 + 4);
            const float4 b0v = *(const float4*)(y2s + lane * 8);
            const float4 b1v = *(const float4*)(y2s + lane * 8 + 4);
            y1v[0] = a0.x; y1v[1] = a0.y; y1v[2] = a0.z; y1v[3] = a0.w;
            y1v[4] = a1.x; y1v[5] = a1.y; y1v[6] = a1.z; y1v[7] = a1.w;
            y2v[0] = b0v.x; y2v[1] = b0v.y; y2v[2] = b0v.z; y2v[3] = b0v.w;
            y2v[4] = b1v.x; y2v[5] = b1v.y; y2v[6] = b1v.z; y2v[7] = b1v.w;
        }

        // prod = w.(G2 w): butterfly (range too wide for fixed point)
        float pr = 0.f;
        #pragma unroll
        for (int k = 0; k < 8; k++) pr = fmaf(wv[k], y2v[k], pr);
        #pragma unroll
        for (int o = 16; o; o >>= 1) pr += __shfl_xor_sync(0xFFFFFFFFu, pr, o);
        const float kin = KAPPA * rsqrtf(fmaxf(pr, 1e-12f));

        float v[8];
        #pragma unroll
        for (int k = 0; k < 8; k++) {
            const float grad = -mu_r[k] + LAMBD * y1v[k] + kin * y2v[k];
            v[k] = wv[k] - step * grad;
        }

        // Warm-started Newton, 2 steps with FIXED-POINT REDUX reductions
        // (s quantized at 2^-22; tau error ~1e-7 -> negligible; fallback =
        // exact float loop when the active set changed).
        float tt = tau;
        float s0f = 0.f; int c0 = 0;
        #pragma unroll
        for (int k = 0; k < 8; k++) {
            const float d = v[k] - tt;
            if (d > 0.f) { s0f += d; c0++; }
        }
        int s0i = __float2int_rn(s0f * FXS);
        c0 = __reduce_add_sync(0xFFFFFFFFu, c0);
        s0i = __reduce_add_sync(0xFFFFFFFFu, s0i);
        const float s0 = (float)s0i * FXS_INV;
        if (c0 > 0) tt += (s0 - 1.0f) / (float)c0;

        float s1f = 0.f; int c1 = 0;
        #pragma unroll
        for (int k = 0; k < 8; k++) {
            const float d = v[k] - tt;
            if (d > 0.f) { s1f += d; c1++; }
        }
        int s1i = __float2int_rn(s1f * FXS);
        c1 = __reduce_add_sync(0xFFFFFFFFu, c1);
        s1i = __reduce_add_sync(0xFFFFFFFFu, s1i);
        const float s1 = (float)s1i * FXS_INV;

        if (c0 == 0 || c1 == 0 || fabsf(s1 - 1.0f) > 1e-5f) {
            // fallback: exact float-butterfly Newton from the lower bound
            float S = 0.f;
            #pragma unroll
            for (int k = 0; k < 8; k++) S += v[k];
            #pragma unroll
            for (int o = 16; o; o >>= 1) S += __shfl_xor_sync(0xFFFFFFFFu, S, o);
            tt = (S - 1.0f) * (1.0f / (float)N_SZ);
            for (int ni = 0; ni < 10; ni++) {
                float s = 0.f; int cnt = 0;
                #pragma unroll
                for (int k = 0; k < 8; k++) {
                    const float d = v[k] - tt;
                    if (d > 0.f) { s += d; cnt++; }
                }
                cnt = __reduce_add_sync(0xFFFFFFFFu, cnt);
                #pragma unroll
                for (int o = 16; o; o >>= 1)
                    s += __shfl_xor_sync(0xFFFFFFFFu, s, o);
                if (cnt == 0) break;
                const float delta = (s - 1.0f) / (float)cnt;
                tt += delta;
                if (fabsf(delta) <= 1e-10f) break;
            }
        }
        tau = tt;

        #pragma unroll
        for (int k = 0; k < 8; k++) {
            wv[k] = fmaxf(v[k] - tau, 0.f);
            const __half h = __float2half_rn(wv[k]);
            asm volatile("st.shared.u16 [%0], %1;"
                         :: "r"(wpriv + (uint32_t)k * 64 + lane_woff),
                            "h"(__half_as_ushort(h)) : "memory");
        }
        __syncwarp();
    }

    // ---- final clamp + renormalize (warp 0 writes) ----
    if (r == 0) {
        float s = 0.f;
        #pragma unroll
        for (int k = 0; k < 8; k++) { wv[k] = fmaxf(wv[k], 0.f); s += wv[k]; }
        #pragma unroll
        for (int o = 16; o; o >>= 1) s += __shfl_xor_sync(0xFFFFFFFFu, s, o);
        const float inv = 1.0f / (s + 1e-12f);
        #pragma unroll
        for (int k = 0; k < 8; k++)
            out[(size_t)b * N_SZ + lane + (k << 5)] = wv[k] * inv;
    }
}

// ---------------------------------------------------------------------------
// Launcher
// ---------------------------------------------------------------------------
extern "C" void kernel_launch(void* const* d_in, const int* in_sizes, int n_in,
                              void* d_out, int out_size) {
    const float* mu = (const float*)d_in[0];
    const float* U  = (const float*)d_in[1];
    const float* A  = (const float*)d_in[2];
    float* out = (float*)d_out;

    cudaFuncSetAttribute(syrk16_kernel, cudaFuncAttributeMaxDynamicSharedMemorySize,
                         SYRK_SMEM);
    cudaFuncSetAttribute(pgd_mma_kernel, cudaFuncAttributeMaxDynamicSharedMemorySize,
                         SM_TOTAL);

    syrk16_kernel<<<2 * B_SZ, 256, SYRK_SMEM>>>(U, A);
    pgd_mma_kernel<<<B_SZ, 256, SM_TOTAL>>>(mu, out);
}